// round 15
// baseline (speedup 1.0000x reference)
#include <cuda_runtime.h>
#include <cuda_bf16.h>
#include <math.h>
#include <stdint.h>

#define Bq 128
#define Hq 512
#define LCq 256
#define LTq 64
#define Vq 27
#define NLq 2
#define H3q (3*Hq)
#define KT 32
#define Mq (LCq*Bq)

// ---------------- scratch ----------------
__device__ float g_gi[(size_t)2*Mq*H3q];
__device__ float g_y0[(size_t)Mq*2*Hq];
__device__ float g_y1[(size_t)Mq*2*Hq];
__device__ float g_v [(size_t)Mq*Hq];
__device__ float g_vn[Mq];
__device__ float g_hd[2][NLq][Bq*Hq];
__device__ float g_a [Bq*Hq];
__device__ float g_hid[Bq*Hq];
__device__ int   g_vecin[Bq];
__device__ unsigned g_barc[2][4*32];
__device__ unsigned g_dbar[4*32];

// bf16 hi/lo decompositions
__device__ __nv_bfloat16 g_xr_h[(size_t)Mq*Hq],   g_xr_l[(size_t)Mq*Hq];
__device__ __nv_bfloat16 g_y0_h[(size_t)Mq*2*Hq], g_y0_l[(size_t)Mq*2*Hq];
__device__ __nv_bfloat16 g_y1_h[(size_t)Mq*2*Hq], g_y1_l[(size_t)Mq*2*Hq];
__device__ __nv_bfloat16 g_w0_h[2*H3q*Hq],   g_w0_l[2*H3q*Hq];
__device__ __nv_bfloat16 g_w1_h[2*H3q*2*Hq], g_w1_l[2*H3q*2*Hq];
__device__ __nv_bfloat16 g_wb_h[Hq*2*Hq],    g_wb_l[Hq*2*Hq];
// decoder bf16
__device__ __nv_bfloat16 g_dwih_h[NLq*H3q*Hq], g_dwih_l[NLq*H3q*Hq];
__device__ __nv_bfloat16 g_dwhh_h[NLq*H3q*Hq], g_dwhh_l[NLq*H3q*Hq];
__device__ __nv_bfloat16 g_emb_h[Vq*Hq], g_emb_l[Vq*Hq];
__device__ __nv_bfloat16 g_hdh[2][NLq][Bq*Hq], g_hdl[2][NLq][Bq*Hq];

// ---------------- warp-mma primitives ----------------
__device__ __forceinline__ uint32_t smem_u32(const void* p) {
    uint32_t a;
    asm("{ .reg .u64 t; cvta.to.shared.u64 t, %1; cvt.u32.u64 %0, t; }" : "=r"(a) : "l"(p));
    return a;
}
__device__ __forceinline__ void ldsm4(uint32_t& r0, uint32_t& r1, uint32_t& r2, uint32_t& r3,
                                      uint32_t a) {
    asm volatile("ldmatrix.sync.aligned.m8n8.x4.shared.b16 {%0,%1,%2,%3}, [%4];"
        : "=r"(r0), "=r"(r1), "=r"(r2), "=r"(r3) : "r"(a));
}
__device__ __forceinline__ void ldsm2(uint32_t& r0, uint32_t& r1, uint32_t a) {
    asm volatile("ldmatrix.sync.aligned.m8n8.x2.shared.b16 {%0,%1}, [%2];"
        : "=r"(r0), "=r"(r1) : "r"(a));
}
__device__ __forceinline__ void mma_bf16(float* c, const uint32_t* a, const uint32_t* b) {
    asm volatile("mma.sync.aligned.m16n8k16.row.col.f32.bf16.bf16.f32 "
        "{%0,%1,%2,%3}, {%4,%5,%6,%7}, {%8,%9}, {%0,%1,%2,%3};"
        : "+f"(c[0]), "+f"(c[1]), "+f"(c[2]), "+f"(c[3])
        : "r"(a[0]), "r"(a[1]), "r"(a[2]), "r"(a[3]), "r"(b[0]), "r"(b[1]));
}
__device__ __forceinline__ void cpa16(uint32_t s, const void* g) {
    asm volatile("cp.async.ca.shared.global [%0], [%1], 16;" :: "r"(s), "l"(g));
}
__device__ __forceinline__ void cpa16cg(uint32_t s, const void* g) {
    asm volatile("cp.async.cg.shared.global [%0], [%1], 16;" :: "r"(s), "l"(g));
}
#define CP_COMMIT()  asm volatile("cp.async.commit_group;" ::: "memory")
#define CP_WAIT_1()  asm volatile("cp.async.wait_group 1;" ::: "memory")
#define CP_WAIT_0()  asm volatile("cp.async.wait_group 0;" ::: "memory")

// ---------------- fp32 -> bf16 hi/lo split ----------------
__global__ void k_cvt(const float* __restrict__ s, __nv_bfloat16* __restrict__ hi,
                      __nv_bfloat16* __restrict__ lo, int n4) {
    int i = blockIdx.x * blockDim.x + threadIdx.x;
    if (i >= n4) return;
    float4 v = *(const float4*)(s + (size_t)i*4);
    __nv_bfloat16 h0 = __float2bfloat16(v.x), h1 = __float2bfloat16(v.y);
    __nv_bfloat16 h2 = __float2bfloat16(v.z), h3 = __float2bfloat16(v.w);
    __nv_bfloat162 hA, hB, lA, lB;
    hA.x = h0; hA.y = h1; hB.x = h2; hB.y = h3;
    lA.x = __float2bfloat16(v.x - __bfloat162float(h0));
    lA.y = __float2bfloat16(v.y - __bfloat162float(h1));
    lB.x = __float2bfloat16(v.z - __bfloat162float(h2));
    lB.y = __float2bfloat16(v.w - __bfloat162float(h3));
    *(__nv_bfloat162*)(hi + (size_t)i*4)     = hA;
    *(__nv_bfloat162*)(hi + (size_t)i*4 + 2) = hB;
    *(__nv_bfloat162*)(lo + (size_t)i*4)     = lA;
    *(__nv_bfloat162*)(lo + (size_t)i*4 + 2) = lB;
}

// ---------------- encoder input projection (fused hi/lo + barrier reset) -------
__global__ void k_proj(const float* __restrict__ x, const float* __restrict__ W_enc,
                       const float* __restrict__ b_enc) {
    int idx = blockIdx.x * blockDim.x + threadIdx.x;
    if (blockIdx.x == 0 && threadIdx.x == 0) {
        for (int i = 0; i < 2; i++)
            for (int j = 0; j < 4; j++) g_barc[i][j*32] = 0;
        for (int j = 0; j < 4; j++) g_dbar[j*32] = 0;
    }
    if (idx >= Mq*Hq) return;
    int h = idx % Hq; int bl = idx / Hq; int b = bl % Bq; int l = bl / Bq;
    float v = x[(size_t)b*2*LCq + l] * W_enc[h*2]
            + x[(size_t)b*2*LCq + LCq + l] * W_enc[h*2+1] + b_enc[h];
    __nv_bfloat16 hv = __float2bfloat16(v);
    g_xr_h[idx] = hv;
    g_xr_l[idx] = __float2bfloat16(v - __bfloat162float(hv));
}

// ---------------- tensor-core GEMM: CTA 128x128, warp 32x64, cp.async ---------
#define AROW 40
#define GT (128*AROW)
#define GEMM_SMEM (8*GT*2)
__global__ void __launch_bounds__(256) k_gemm_mma(
        const __nv_bfloat16* __restrict__ Ah, const __nv_bfloat16* __restrict__ Al,
        const __nv_bfloat16* __restrict__ Wh, const __nv_bfloat16* __restrict__ Wl,
        const float* __restrict__ bias, float* __restrict__ C,
        int K, int Nld, size_t wStrideZ, int bStrideZ, size_t cStrideZ) {
    extern __shared__ __nv_bfloat16 gsm[];
    __nv_bfloat16* sAh = gsm;
    __nv_bfloat16* sAl = gsm + 2*GT;
    __nv_bfloat16* sWh = gsm + 4*GT;
    __nv_bfloat16* sWl = gsm + 6*GT;

    int tid = threadIdx.x, wid = tid >> 5, lane = tid & 31;
    int z = blockIdx.z;
    const __nv_bfloat16* Whz = Wh + (size_t)z*wStrideZ;
    const __nv_bfloat16* Wlz = Wl + (size_t)z*wStrideZ;
    const float* bias_z = bias + (size_t)z*bStrideZ;
    float* C_z = C + (size_t)z*cStrideZ;
    int col0 = blockIdx.x * 128, row0 = blockIdx.y * 128;
    int wm = (wid & 3) * 32, wn = (wid >> 2) * 64;

    float acc[2][8][4];
    #pragma unroll
    for (int i = 0; i < 2; i++)
        #pragma unroll
        for (int j = 0; j < 8; j++)
            #pragma unroll
            for (int k = 0; k < 4; k++) acc[i][j][k] = 0.f;

    uint32_t aBase = smem_u32(sAh), alBase = smem_u32(sAl);
    uint32_t wBase = smem_u32(sWh), wlBase = smem_u32(sWl);
    int aRow = wm + (lane & 15);
    int aCol = (lane >> 4) * 8;
    int g = lane >> 3;
    int bRow = wn + (lane & 7) + ((g >> 1) & 1) * 8;
    int bCol = (g & 1) * 8;

    int r0 = tid >> 2, c0 = tid & 3;
    int r1 = (tid + 256) >> 2, c1 = (tid + 256) & 3;
    uint32_t sOff0 = (uint32_t)((r0*AROW + c0*8) * 2);
    uint32_t sOff1 = (uint32_t)((r1*AROW + c1*8) * 2);
    size_t goA0 = (size_t)(row0 + r0)*K + c0*8;
    size_t goA1 = (size_t)(row0 + r1)*K + c1*8;
    size_t goW0 = (size_t)(col0 + r0)*K + c0*8;
    size_t goW1 = (size_t)(col0 + r1)*K + c1*8;

    int nk = K >> 5;
    {
        cpa16(aBase  + sOff0, Ah + goA0);  cpa16(aBase  + sOff1, Ah + goA1);
        cpa16(alBase + sOff0, Al + goA0);  cpa16(alBase + sOff1, Al + goA1);
        cpa16(wBase  + sOff0, Whz + goW0); cpa16(wBase  + sOff1, Whz + goW1);
        cpa16(wlBase + sOff0, Wlz + goW0); cpa16(wlBase + sOff1, Wlz + goW1);
        CP_COMMIT();
    }
    int buf = 0;
    for (int kc = 0; kc < nk; kc++) {
        if (kc + 1 < nk) {
            int kn = (kc + 1) << 5;
            uint32_t bo = (uint32_t)((buf ^ 1) * GT * 2);
            cpa16(aBase  + bo + sOff0, Ah + goA0 + kn);  cpa16(aBase  + bo + sOff1, Ah + goA1 + kn);
            cpa16(alBase + bo + sOff0, Al + goA0 + kn);  cpa16(alBase + bo + sOff1, Al + goA1 + kn);
            cpa16(wBase  + bo + sOff0, Whz + goW0 + kn); cpa16(wBase  + bo + sOff1, Whz + goW1 + kn);
            cpa16(wlBase + bo + sOff0, Wlz + goW0 + kn); cpa16(wlBase + bo + sOff1, Wlz + goW1 + kn);
            CP_COMMIT();
            CP_WAIT_1();
        } else {
            CP_WAIT_0();
        }
        __syncthreads();

        uint32_t abH = aBase  + (uint32_t)(buf*GT*2);
        uint32_t abL = alBase + (uint32_t)(buf*GT*2);
        uint32_t wbH = wBase  + (uint32_t)(buf*GT*2);
        uint32_t wbL = wlBase + (uint32_t)(buf*GT*2);

        #pragma unroll
        for (int ks = 0; ks < 2; ks++) {
            uint32_t ah[2][4], al[2][4];
            #pragma unroll
            for (int mi = 0; mi < 2; mi++) {
                uint32_t off = (uint32_t)(((aRow + mi*16)*AROW + ks*16 + aCol) * 2);
                ldsm4(ah[mi][0], ah[mi][1], ah[mi][2], ah[mi][3], abH + off);
                ldsm4(al[mi][0], al[mi][1], al[mi][2], al[mi][3], abL + off);
            }
            #pragma unroll
            for (int ng = 0; ng < 4; ng++) {
                uint32_t bh[4], bl[4];
                uint32_t off = (uint32_t)(((bRow + ng*16)*AROW + ks*16 + bCol) * 2);
                ldsm4(bh[0], bh[1], bh[2], bh[3], wbH + off);
                ldsm4(bl[0], bl[1], bl[2], bl[3], wbL + off);
                #pragma unroll
                for (int mi = 0; mi < 2; mi++)
                    #pragma unroll
                    for (int half = 0; half < 2; half++) {
                        float* c = acc[mi][ng*2 + half];
                        mma_bf16(c, ah[mi], &bh[half*2]);
                        mma_bf16(c, ah[mi], &bl[half*2]);
                        mma_bf16(c, al[mi], &bh[half*2]);
                    }
            }
        }
        __syncthreads();
        buf ^= 1;
    }

    #pragma unroll
    for (int mi = 0; mi < 2; mi++) {
        int r_ = row0 + wm + mi*16 + (lane >> 2);
        #pragma unroll
        for (int ni = 0; ni < 8; ni++) {
            int c_ = col0 + wn + ni*8 + (lane & 3)*2;
            float b0 = bias_z[c_], b1 = bias_z[c_ + 1];
            float2 o0 = { acc[mi][ni][0] + b0, acc[mi][ni][1] + b1 };
            float2 o1 = { acc[mi][ni][2] + b0, acc[mi][ni][3] + b1 };
            *(float2*)(C_z + (size_t)r_*Nld + c_)       = o0;
            *(float2*)(C_z + (size_t)(r_ + 8)*Nld + c_) = o1;
        }
    }
}

// ---------------- persistent MMA encoder GRU layer (R11 winner) ----------------
#define WP 520
#define AP 136
#define ENC_SMEM ((96*WP + 4*64*AP) * 2)
__global__ void __launch_bounds__(256, 1) k_enc_mma(
        const float* __restrict__ Whh2, const float* __restrict__ bhh2, int layer) {
    extern __shared__ __nv_bfloat16 smb[];
    __nv_bfloat16* sWh = smb;
    __nv_bfloat16* sWl = smb + 48*WP;
    __nv_bfloat16* sAh = smb + 96*WP;
    __nv_bfloat16* sAl = smb + 96*WP + 2*64*AP;

    float* Y = layer ? g_y1 : g_y0;
    __nv_bfloat16* Yh = layer ? g_y1_h : g_y0_h;
    __nv_bfloat16* Yl = layer ? g_y1_l : g_y0_l;

    int bid = blockIdx.x;
    int dirv = bid >> 6;
    int rem = bid & 63;
    int cg = rem & 31;
    int bg = rem >> 5;
    int gc0 = cg * 16;
    int row0 = bg * 64;
    unsigned grp = ((unsigned)dirv << 1) | (unsigned)bg;

    int tid = threadIdx.x, wid = tid >> 5, lane = tid & 31;
    int wm = (wid & 3) * 16;
    int ws = wid >> 2;

    const float* Whh = Whh2 + (size_t)dirv*H3q*Hq;
    const float* bhh = bhh2 + dirv*H3q;

    for (int u = tid; u < 48*128; u += 256) {
        int rrow = u >> 7, kq = u & 127;
        int g = rrow >> 4, c = rrow & 15;
        float4 w = __ldg((const float4*)(Whh + (size_t)(g*Hq + gc0 + c)*Hq) + kq);
        __nv_bfloat16 h0 = __float2bfloat16(w.x), h1 = __float2bfloat16(w.y);
        __nv_bfloat16 h2 = __float2bfloat16(w.z), h3 = __float2bfloat16(w.w);
        __nv_bfloat162 hh0; hh0.x = h0; hh0.y = h1;
        __nv_bfloat162 hh1; hh1.x = h2; hh1.y = h3;
        __nv_bfloat162 ll0, ll1;
        ll0.x = __float2bfloat16(w.x - __bfloat162float(h0));
        ll0.y = __float2bfloat16(w.y - __bfloat162float(h1));
        ll1.x = __float2bfloat16(w.z - __bfloat162float(h2));
        ll1.y = __float2bfloat16(w.w - __bfloat162float(h3));
        *(__nv_bfloat162*)(sWh + rrow*WP + kq*4)     = hh0;
        *(__nv_bfloat162*)(sWh + rrow*WP + kq*4 + 2) = hh1;
        *(__nv_bfloat162*)(sWl + rrow*WP + kq*4)     = ll0;
        *(__nv_bfloat162*)(sWl + rrow*WP + kq*4 + 2) = ll1;
    }
    int cA = gc0 + ws*8 + 2*(lane & 3);
    float br0 = __ldg(bhh + cA),        br1 = __ldg(bhh + cA + 1);
    float bz0 = __ldg(bhh + 512 + cA),  bz1 = __ldg(bhh + 512 + cA + 1);
    float bn0 = __ldg(bhh + 1024 + cA), bn1 = __ldg(bhh + 1024 + cA + 1);
    __syncthreads();

    uint32_t aBaseH = smem_u32(sAh), aBaseL = smem_u32(sAl);
    uint32_t wBaseH = smem_u32(sWh), wBaseL = smem_u32(sWl);
    uint32_t aOff = (uint32_t)(((wm + (lane & 15))*AP + (lane >> 4)*8) * 2);
    int bRow = ws*8 + (lane & 7);
    uint32_t bColOff = (uint32_t)((((lane >> 3) & 1) * 8) * 2);

    int sr[4], sc[4];
    #pragma unroll
    for (int i = 0; i < 4; i++) {
        int slot = tid + i*256;
        sr[i] = slot >> 4; sc[i] = slot & 15;
    }

    float2 hpreg[2];
    hpreg[0] = make_float2(0.f, 0.f);
    hpreg[1] = make_float2(0.f, 0.f);

    for (int s = 0; s < LCq; s++) {
        int t = dirv ? (LCq-1-s) : s;
        int tprev = dirv ? (t+1) : (t-1);

        const float* gi_t = g_gi + ((size_t)dirv*LCq + t)*Bq*H3q;
        float2 gr[2], gz[2], gn[2];
        #pragma unroll
        for (int rr = 0; rr < 2; rr++) {
            int b = row0 + wm + (lane >> 2) + rr*8;
            const float* gib = gi_t + (size_t)b*H3q;
            gr[rr] = __ldg((const float2*)(gib + cA));
            gz[rr] = __ldg((const float2*)(gib + 512 + cA));
            gn[rr] = __ldg((const float2*)(gib + 1024 + cA));
        }

        float acc[3][4];
        #pragma unroll
        for (int g = 0; g < 3; g++) {
            acc[g][0] = acc[g][1] = acc[g][2] = acc[g][3] = 0.f;
        }

        if (s > 0) {
            const __nv_bfloat16* Ahp = Yh + ((size_t)tprev*Bq)*2*Hq + (size_t)dirv*Hq;
            const __nv_bfloat16* Alp = Yl + ((size_t)tprev*Bq)*2*Hq + (size_t)dirv*Hq;
            uint4 ph[4], pl[4];
            #pragma unroll
            for (int i = 0; i < 4; i++) {
                ph[i] = __ldcg((const uint4*)(Ahp + (size_t)(row0 + sr[i])*2*Hq + sc[i]*8));
                pl[i] = __ldcg((const uint4*)(Alp + (size_t)(row0 + sr[i])*2*Hq + sc[i]*8));
            }
            int buf = 0;
            for (int kc = 0; kc < 4; kc++) {
                __nv_bfloat16* dAh = sAh + buf*64*AP;
                __nv_bfloat16* dAl = sAl + buf*64*AP;
                #pragma unroll
                for (int i = 0; i < 4; i++) {
                    *(uint4*)(dAh + sr[i]*AP + sc[i]*8) = ph[i];
                    *(uint4*)(dAl + sr[i]*AP + sc[i]*8) = pl[i];
                }
                __syncthreads();
                if (kc < 3) {
                    int k1 = (kc + 1)*128;
                    #pragma unroll
                    for (int i = 0; i < 4; i++) {
                        ph[i] = __ldcg((const uint4*)(Ahp + (size_t)(row0 + sr[i])*2*Hq + k1 + sc[i]*8));
                        pl[i] = __ldcg((const uint4*)(Alp + (size_t)(row0 + sr[i])*2*Hq + k1 + sc[i]*8));
                    }
                }
                int k0 = kc*128;
                uint32_t abH = aBaseH + (uint32_t)(buf*64*AP*2);
                uint32_t abL = aBaseL + (uint32_t)(buf*64*AP*2);
                #pragma unroll
                for (int ks = 0; ks < 8; ks++) {
                    uint32_t ah[4], al[4];
                    uint32_t ao = aOff + (uint32_t)(ks*32);
                    ldsm4(ah[0], ah[1], ah[2], ah[3], abH + ao);
                    ldsm4(al[0], al[1], al[2], al[3], abL + ao);
                    #pragma unroll
                    for (int g = 0; g < 3; g++) {
                        uint32_t bh[2], bl[2];
                        uint32_t wo = (uint32_t)((((g*16 + bRow)*WP) + k0 + ks*16)*2) + bColOff;
                        ldsm2(bh[0], bh[1], wBaseH + wo);
                        ldsm2(bl[0], bl[1], wBaseL + wo);
                        mma_bf16(acc[g], ah, bh);
                        mma_bf16(acc[g], ah, bl);
                        mma_bf16(acc[g], al, bh);
                    }
                }
                __syncthreads();
                buf ^= 1;
            }
        }

        #pragma unroll
        for (int rr = 0; rr < 2; rr++) {
            int b = row0 + wm + (lane >> 2) + rr*8;
            float r0v = 1.f/(1.f + expf(-(gr[rr].x + acc[0][rr*2]   + br0)));
            float r1v = 1.f/(1.f + expf(-(gr[rr].y + acc[0][rr*2+1] + br1)));
            float z0v = 1.f/(1.f + expf(-(gz[rr].x + acc[1][rr*2]   + bz0)));
            float z1v = 1.f/(1.f + expf(-(gz[rr].y + acc[1][rr*2+1] + bz1)));
            float n0v = tanhf(gn[rr].x + r0v*(acc[2][rr*2]   + bn0));
            float n1v = tanhf(gn[rr].y + r1v*(acc[2][rr*2+1] + bn1));
            float h0v = (1.f - z0v)*n0v + z0v*hpreg[rr].x;
            float h1v = (1.f - z1v)*n1v + z1v*hpreg[rr].y;
            hpreg[rr] = make_float2(h0v, h1v);
            size_t o = ((size_t)t*Bq + b)*2*Hq + (size_t)dirv*Hq + cA;
            if (layer == 0 && s == LCq-1)
                *(float2*)(Y + o) = hpreg[rr];
            __nv_bfloat16 bh0 = __float2bfloat16(h0v), bh1 = __float2bfloat16(h1v);
            __nv_bfloat162 hv; hv.x = bh0; hv.y = bh1;
            __nv_bfloat162 lv;
            lv.x = __float2bfloat16(h0v - __bfloat162float(bh0));
            lv.y = __float2bfloat16(h1v - __bfloat162float(bh1));
            *(__nv_bfloat162*)(Yh + o) = hv;
            *(__nv_bfloat162*)(Yl + o) = lv;
        }

        __threadfence();
        __syncthreads();
        if (tid == 0) {
            atomicAdd(&g_barc[layer][grp*32], 1u);
            unsigned target = 32u * (unsigned)(s + 1);
            while (*(volatile unsigned*)&g_barc[layer][grp*32] < target) { }
        }
        __syncthreads();
    }
}

// ---------------- v row norms ----------------
__global__ void k_vn() {
    int row = blockIdx.x;
    int tid = threadIdx.x;
    const float* vr = g_v + (size_t)row*Hq;
    float s = 0.f;
    for (int k = tid; k < Hq; k += 128) { float x = vr[k]; s = fmaf(x, x, s); }
    __shared__ float red[128];
    red[tid] = s; __syncthreads();
    for (int o = 64; o > 0; o >>= 1) { if (tid < o) red[tid] += red[tid + o]; __syncthreads(); }
    if (tid == 0) g_vn[row] = fmaxf(sqrtf(red[0]), 1e-8f);
}

// ---------------- decoder init (fp32 + hi/lo) ----------------
__global__ void k_initdec() {
    int idx = blockIdx.x * blockDim.x + threadIdx.x;
    if (idx < Bq) g_vecin[idx] = 0;
    if (idx < Bq*Hq) {
        int b = idx / Hq, h = idx % Hq;
        float h0 = g_y0[((size_t)(LCq-1)*Bq + b)*2*Hq + h];
        float h1 = g_y0[((size_t)b)*2*Hq + Hq + h];
        g_hd[0][0][idx] = h0;
        g_hd[0][1][idx] = h1;
        __nv_bfloat16 a = __float2bfloat16(h0);
        __nv_bfloat16 c = __float2bfloat16(h1);
        g_hdh[0][0][idx] = a;
        g_hdl[0][0][idx] = __float2bfloat16(h0 - __bfloat162float(a));
        g_hdh[0][1][idx] = c;
        g_hdl[0][1][idx] = __float2bfloat16(h1 - __bfloat162float(c));
    }
}

// ================= persistent decoder =================
// gru stage double-buffered: per buffer 320 rows x 72 bf16 (W 96 | Wl 96 | X 32 | Xl 32 | H 32 | Hl 32)
#define DBUFE (320*72)
#define DEC_SMEM (2*DBUFE*2 + 4*32*17*4 + 128 + 128)

// group-local barrier: the 4 bg-groups are fully independent decoders
__device__ __forceinline__ void dec_gridbar(unsigned seq) {
    __threadfence();
    __syncthreads();
    if (threadIdx.x == 0) {
        unsigned grp = blockIdx.x >> 5;
        atomicAdd(&g_dbar[grp*32], 1u);
        unsigned t = 32u * seq;
        while (*(volatile unsigned*)&g_dbar[grp*32] < t) { }
    }
    __syncthreads();
}

__device__ void dec_gru_stage(char* sm, int l, int p, float* hreg,
        const __nv_bfloat16* __restrict__ Wih_h, const __nv_bfloat16* __restrict__ Wih_l,
        const __nv_bfloat16* __restrict__ Whh_h, const __nv_bfloat16* __restrict__ Whh_l,
        const float* __restrict__ bih, const float* __restrict__ bhh) {
    float* sAcc = (float*)(sm + 2*DBUFE*2);
    int* vs = (int*)(sm + 2*DBUFE*2 + 4*32*17*4);

    int tid = threadIdx.x, lane = tid & 31, wid = tid >> 5;
    int cg = blockIdx.x & 31, bg = blockIdx.x >> 5;
    int gc0 = cg * 16, row0 = bg * 32;
    int wm16 = (wid & 1) * 16;
    int wq = wid >> 1;

    if (l == 0 && tid < 32) vs[tid] = __ldcg(&g_vecin[row0 + tid]);

    const __nv_bfloat16* Hh = g_hdh[p][l];
    const __nv_bfloat16* Hl = g_hdl[p][l];
    const __nv_bfloat16* Xh_g = (l == 0) ? g_emb_h : g_hdh[1-p][0];
    const __nv_bfloat16* Xl_g = (l == 0) ? g_emb_l : g_hdl[1-p][0];

    float acc[2][4] = {{0,0,0,0},{0,0,0,0}};

    uint32_t sBase = smem_u32(sm);
    // element offsets within a buffer
    const int OW = 0, OWL = 96*72, OX = 192*72, OXL = 224*72, OH = 256*72, OHL = 288*72;

    uint32_t aOffBase = (uint32_t)(((wm16 + (lane & 15))*72 + (lane >> 4)*8) * 2);
    int bRowIn = (lane & 7) + ((lane >> 4) & 1)*8;
    uint32_t bColOff = (uint32_t)((((lane >> 3) & 1) * 8) * 2);

    int srr = tid >> 3, sku = tid & 7;

    __syncthreads();   // vs visible before staging chunk 0

    // ---- staging helper (inlined twice) ----
    #define DEC_STAGE(kcv, bs) do { \
        int k0_ = (kcv) * 64; \
        uint32_t bofs_ = sBase + (uint32_t)((bs) * DBUFE * 2); \
        _Pragma("unroll") \
        for (int i_ = 0; i_ < 3; i_++) { \
            int u_ = tid + i_*256; \
            int rr_ = u_ >> 3, ku_ = u_ & 7; \
            int grow_ = rr_ < 48 ? rr_ : rr_ - 48; \
            int g_ = grow_ >> 4, c_ = grow_ & 15; \
            size_t src_ = (size_t)(g_*Hq + gc0 + c_)*Hq + k0_ + ku_*8; \
            const __nv_bfloat16* MH_ = rr_ < 48 ? Wih_h : Whh_h; \
            const __nv_bfloat16* ML_ = rr_ < 48 ? Wih_l : Whh_l; \
            cpa16cg(bofs_ + (uint32_t)((OW  + rr_*72 + ku_*8) * 2), MH_ + src_); \
            cpa16cg(bofs_ + (uint32_t)((OWL + rr_*72 + ku_*8) * 2), ML_ + src_); \
        } \
        { \
            size_t xoff_ = (l == 0) ? (size_t)vs[srr]*Hq + k0_ + sku*8 \
                                    : (size_t)(row0 + srr)*Hq + k0_ + sku*8; \
            size_t hoff_ = (size_t)(row0 + srr)*Hq + k0_ + sku*8; \
            cpa16cg(bofs_ + (uint32_t)((OX  + srr*72 + sku*8) * 2), Xh_g + xoff_); \
            cpa16cg(bofs_ + (uint32_t)((OXL + srr*72 + sku*8) * 2), Xl_g + xoff_); \
            cpa16cg(bofs_ + (uint32_t)((OH  + srr*72 + sku*8) * 2), Hh + hoff_); \
            cpa16cg(bofs_ + (uint32_t)((OHL + srr*72 + sku*8) * 2), Hl + hoff_); \
        } \
    } while (0)

    DEC_STAGE(0, 0);
    CP_COMMIT();

    int buf = 0;
    for (int kc = 0; kc < 8; kc++) {
        if (kc < 7) {
            DEC_STAGE(kc + 1, buf ^ 1);
            CP_COMMIT();
            CP_WAIT_1();
        } else {
            CP_WAIT_0();
        }
        __syncthreads();

        uint32_t bb = sBase + (uint32_t)(buf * DBUFE * 2);
        uint32_t aXh = bb + OX*2,  aXl = bb + OXL*2;
        uint32_t aHh = bb + OH*2,  aHl = bb + OHL*2;
        uint32_t wBh = bb,         wBl = bb + OWL*2;

        #pragma unroll
        for (int ks = 0; ks < 4; ks++) {
            uint32_t ao = aOffBase + (uint32_t)(ks*32);
            uint32_t coff = bColOff + (uint32_t)(ks*32);
            if (wq < 2) {
                uint32_t axh[4], axl[4], ahh[4], ahl[4];
                ldsm4(axh[0], axh[1], axh[2], axh[3], aXh + ao);
                ldsm4(axl[0], axl[1], axl[2], axl[3], aXl + ao);
                ldsm4(ahh[0], ahh[1], ahh[2], ahh[3], aHh + ao);
                ldsm4(ahl[0], ahl[1], ahl[2], ahl[3], aHl + ao);
                int gih = wq*16, ghh = 48 + wq*16;
                uint32_t bih_h[4], bih_l[4], bhh_h[4], bhh_l[4];
                uint32_t oi = (uint32_t)(((gih + bRowIn)*72)*2) + coff;
                uint32_t oh = (uint32_t)(((ghh + bRowIn)*72)*2) + coff;
                ldsm4(bih_h[0], bih_h[1], bih_h[2], bih_h[3], wBh + oi);
                ldsm4(bih_l[0], bih_l[1], bih_l[2], bih_l[3], wBl + oi);
                ldsm4(bhh_h[0], bhh_h[1], bhh_h[2], bhh_h[3], wBh + oh);
                ldsm4(bhh_l[0], bhh_l[1], bhh_l[2], bhh_l[3], wBl + oh);
                #pragma unroll
                for (int ni = 0; ni < 2; ni++) {
                    mma_bf16(acc[ni], axh, &bih_h[ni*2]);
                    mma_bf16(acc[ni], axh, &bih_l[ni*2]);
                    mma_bf16(acc[ni], axl, &bih_h[ni*2]);
                    mma_bf16(acc[ni], ahh, &bhh_h[ni*2]);
                    mma_bf16(acc[ni], ahh, &bhh_l[ni*2]);
                    mma_bf16(acc[ni], ahl, &bhh_h[ni*2]);
                }
            } else if (wq == 2) {
                uint32_t axh[4], axl[4], bh[4], bl[4];
                ldsm4(axh[0], axh[1], axh[2], axh[3], aXh + ao);
                ldsm4(axl[0], axl[1], axl[2], axl[3], aXl + ao);
                uint32_t oi = (uint32_t)(((32 + bRowIn)*72)*2) + coff;
                ldsm4(bh[0], bh[1], bh[2], bh[3], wBh + oi);
                ldsm4(bl[0], bl[1], bl[2], bl[3], wBl + oi);
                #pragma unroll
                for (int ni = 0; ni < 2; ni++) {
                    mma_bf16(acc[ni], axh, &bh[ni*2]);
                    mma_bf16(acc[ni], axh, &bl[ni*2]);
                    mma_bf16(acc[ni], axl, &bh[ni*2]);
                }
            } else {
                uint32_t ahh[4], ahl[4], bh[4], bl[4];
                ldsm4(ahh[0], ahh[1], ahh[2], ahh[3], aHh + ao);
                ldsm4(ahl[0], ahl[1], ahl[2], ahl[3], aHl + ao);
                uint32_t oh = (uint32_t)(((80 + bRowIn)*72)*2) + coff;
                ldsm4(bh[0], bh[1], bh[2], bh[3], wBh + oh);
                ldsm4(bl[0], bl[1], bl[2], bl[3], wBl + oh);
                #pragma unroll
                for (int ni = 0; ni < 2; ni++) {
                    mma_bf16(acc[ni], ahh, &bh[ni*2]);
                    mma_bf16(acc[ni], ahh, &bl[ni*2]);
                    mma_bf16(acc[ni], ahl, &bh[ni*2]);
                }
            }
        }
        __syncthreads();
        buf ^= 1;
    }
    #undef DEC_STAGE

    {
        int r0 = wm16 + (lane >> 2);
        #pragma unroll
        for (int ni = 0; ni < 2; ni++) {
            int cb = ni*8 + (lane & 3)*2;
            sAcc[(wq*32 + r0)*17 + cb]       = acc[ni][0];
            sAcc[(wq*32 + r0)*17 + cb + 1]   = acc[ni][1];
            sAcc[(wq*32 + r0+8)*17 + cb]     = acc[ni][2];
            sAcc[(wq*32 + r0+8)*17 + cb + 1] = acc[ni][3];
        }
    }
    __syncthreads();

    #pragma unroll
    for (int j = 0; j < 2; j++) {
        int e = tid + j*256;
        int row = e >> 4, col = e & 15;
        float rv  = sAcc[(0*32 + row)*17 + col];
        float zv  = sAcc[(1*32 + row)*17 + col];
        float nxv = sAcc[(2*32 + row)*17 + col];
        float nhv = sAcc[(3*32 + row)*17 + col];
        int c = gc0 + col, b = row0 + row;
        float rr = 1.f/(1.f + expf(-(rv + __ldg(bih + c) + __ldg(bhh + c))));
        float zz = 1.f/(1.f + expf(-(zv + __ldg(bih + 512 + c) + __ldg(bhh + 512 + c))));
        float nn = tanhf(nxv + __ldg(bih + 1024 + c) + rr*(nhv + __ldg(bhh + 1024 + c)));
        float h = (1.f - zz)*nn + zz*hreg[j];
        hreg[j] = h;
        g_hd[1-p][l][(size_t)b*Hq + c] = h;
        __nv_bfloat16 bh = __float2bfloat16(h);
        g_hdh[1-p][l][(size_t)b*Hq + c] = bh;
        g_hdl[1-p][l][(size_t)b*Hq + c] = __float2bfloat16(h - __bfloat162float(bh));
    }
}

// two-pass attention (R11 winner)
__device__ void dec_attn_stage(char* sm, int t, int p, float* __restrict__ attn_out) {
    float* qs  = (float*)sm;
    float* red = qs + 512;
    float* wsm = red + 256;
    int b = blockIdx.x;
    int tid = threadIdx.x;

    const float* q = g_hd[1-p][1] + (size_t)b*Hq;
    qs[tid]       = __ldcg(q + tid);
    qs[tid + 256] = __ldcg(q + tid + 256);
    __syncthreads();

    float ss = qs[tid]*qs[tid] + qs[tid+256]*qs[tid+256];
    red[tid] = ss; __syncthreads();
    for (int o = 128; o > 0; o >>= 1) { if (tid < o) red[tid] += red[tid + o]; __syncthreads(); }
    float qn = fmaxf(sqrtf(red[0]), 1e-8f);
    __syncthreads();

    const float4* v4 = (const float4*)(g_v + ((size_t)tid*Bq + b)*Hq);
    const float4* q4 = (const float4*)qs;
    float dot = 0.f;
    #pragma unroll 4
    for (int k = 0; k < Hq/4; k++) {
        float4 a = v4[k], c = q4[k];
        dot = fmaf(a.x, c.x, dot); dot = fmaf(a.y, c.y, dot);
        dot = fmaf(a.z, c.z, dot); dot = fmaf(a.w, c.w, dot);
    }
    float sim = dot / (g_vn[(size_t)tid*Bq + b] * qn);

    red[tid] = sim; __syncthreads();
    for (int o = 128; o > 0; o >>= 1) { if (tid < o) red[tid] = fmaxf(red[tid], red[tid+o]); __syncthreads(); }
    float mx = red[0]; __syncthreads();
    float e = expf(sim - mx);
    red[tid] = e; __syncthreads();
    for (int o = 128; o > 0; o >>= 1) { if (tid < o) red[tid] += red[tid + o]; __syncthreads(); }
    float wv = e / red[0];
    wsm[tid] = wv;
    attn_out[((size_t)b*LCq + tid)*LTq + t] = wv;
    __syncthreads();

    for (int h = tid; h < Hq; h += 256) {
        float acc = 0.f;
        for (int l = 0; l < LCq; l++)
            acc = fmaf(wsm[l], g_v[((size_t)l*Bq + b)*Hq + h], acc);
        g_a[(size_t)b*Hq + h] = acc;
    }
}

__device__ void dec_attfc_stage(char* sm, int p,
        const float* __restrict__ Watt, const float* __restrict__ batt) {
    float* Xs  = (float*)sm;
    float* As2 = Xs + 32*33;
    float* Wqs = As2 + 32*33;
    float* Was = Wqs + 32*17;

    const float* X1 = g_hd[1-p][1];
    const float* X2 = g_a;
    int tid = threadIdx.x;
    int tx = tid & 15, ty = tid >> 4;
    int col0 = (blockIdx.x & 31) * 16, row0 = (blockIdx.x >> 5) * 32;

    float acc[2] = {0,0};
    for (int k0 = 0; k0 < Hq; k0 += KT) {
        {
            int r = tid >> 3, kk = (tid & 7) << 2;
            float4 x4 = __ldcg((const float4*)(X1 + (size_t)(row0 + r)*Hq + k0 + kk));
            Xs[kk*33 + r]=x4.x; Xs[(kk+1)*33 + r]=x4.y; Xs[(kk+2)*33 + r]=x4.z; Xs[(kk+3)*33 + r]=x4.w;
            float4 a4 = __ldcg((const float4*)(X2 + (size_t)(row0 + r)*Hq + k0 + kk));
            As2[kk*33 + r]=a4.x; As2[(kk+1)*33 + r]=a4.y; As2[(kk+2)*33 + r]=a4.z; As2[(kk+3)*33 + r]=a4.w;
        }
        #pragma unroll
        for (int j = 0; j < 2; j++) {
            int lin = tid + j*256;
            int c = lin >> 5, k = lin & 31;
            Wqs[k*17 + c] = __ldg(Watt + (size_t)(col0 + c)*2*Hq + k0 + k);
            Was[k*17 + c] = __ldg(Watt + (size_t)(col0 + c)*2*Hq + Hq + k0 + k);
        }
        __syncthreads();
        #pragma unroll
        for (int k = 0; k < KT; k++) {
            float wq = Wqs[k*17 + tx], wa = Was[k*17 + tx];
            #pragma unroll
            for (int i = 0; i < 2; i++) {
                acc[i] = fmaf(Xs[k*33 + ty + 16*i], wq, acc[i]);
                acc[i] = fmaf(As2[k*33 + ty + 16*i], wa, acc[i]);
            }
        }
        __syncthreads();
    }
    int c = col0 + tx;
    #pragma unroll
    for (int i = 0; i < 2; i++) {
        int b = row0 + ty + 16*i;
        g_hid[(size_t)b*Hq + c] = acc[i] + __ldg(batt + c);
    }
}

__device__ void dec_out_stage(char* sm, int t,
        const float* __restrict__ Wout, const float* __restrict__ bout,
        float* __restrict__ vecout) {
    float* hs = (float*)sm;
    float* lg = hs + 512;
    int b = blockIdx.x;
    int tid = threadIdx.x;
    hs[tid]       = __ldcg(&g_hid[(size_t)b*Hq + tid]);
    hs[tid + 256] = __ldcg(&g_hid[(size_t)b*Hq + tid + 256]);
    __syncthreads();

    int wid = tid >> 5, lane = tid & 31;
    for (int j = wid; j < Vq; j += 8) {
        float acc = 0.f;
        for (int k = lane; k < Hq; k += 32)
            acc = fmaf(hs[k], __ldg(Wout + (size_t)j*Hq + k), acc);
        #pragma unroll
        for (int o = 16; o > 0; o >>= 1) acc += __shfl_down_sync(0xffffffffu, acc, o);
        if (lane == 0) lg[j] = acc + __ldg(bout + j);
    }
    __syncthreads();
    if (tid < Vq) vecout[((size_t)b*LTq + t)*Vq + tid] = lg[tid];
    if (tid == 0) {
        int best = 0; float bv = lg[0];
        for (int j = 1; j < Vq; j++) { if (lg[j] > bv) { bv = lg[j]; best = j; } }
        g_vecin[b] = best;
    }
}

__global__ void __launch_bounds__(256, 1) k_dec_pers(
        const float* __restrict__ dec_bih, const float* __restrict__ dec_bhh,
        const float* __restrict__ Watt, const float* __restrict__ batt,
        const float* __restrict__ Wout, const float* __restrict__ bout,
        float* __restrict__ vecout, float* __restrict__ attn_out) {
    extern __shared__ char dsm[];
    int tid = threadIdx.x;
    int cg = blockIdx.x & 31, bg = blockIdx.x >> 5;
    int gc0 = cg * 16, row0 = bg * 32;

    // init per-thread hidden registers from g_hd[0] (written by k_initdec)
    float hdreg[2][2];
    #pragma unroll
    for (int l = 0; l < 2; l++)
        #pragma unroll
        for (int j = 0; j < 2; j++) {
            int e = tid + j*256;
            int row = e >> 4, col = e & 15;
            hdreg[l][j] = g_hd[0][l][(size_t)(row0 + row)*Hq + gc0 + col];
        }

    unsigned seq = 0;
    for (int t = 0; t < LTq; t++) {
        int p = t & 1;
        dec_gru_stage(dsm, 0, p, hdreg[0], g_dwih_h, g_dwih_l, g_dwhh_h, g_dwhh_l,
                      dec_bih, dec_bhh);
        dec_gridbar(++seq);
        dec_gru_stage(dsm, 1, p, hdreg[1],
                      g_dwih_h + (size_t)H3q*Hq, g_dwih_l + (size_t)H3q*Hq,
                      g_dwhh_h + (size_t)H3q*Hq, g_dwhh_l + (size_t)H3q*Hq,
                      dec_bih + H3q, dec_bhh + H3q);
        dec_gridbar(++seq);
        dec_attn_stage(dsm, t, p, attn_out);
        dec_gridbar(++seq);
        dec_attfc_stage(dsm, p, Watt, batt);
        dec_gridbar(++seq);
        dec_out_stage(dsm, t, Wout, bout, vecout);
        dec_gridbar(++seq);
    }
}

// ---------------- final hidden copy ----------------
__global__ void k_hfinal(float* __restrict__ out) {
    int idx = blockIdx.x * blockDim.x + threadIdx.x;
    if (idx < NLq*Bq*Hq) out[idx] = (&g_hd[0][0][0])[idx];
}

// ---------------- launch ----------------
extern "C" void kernel_launch(void* const* d_in, const int* in_sizes, int n_in,
                              void* d_out, int out_size) {
    const float* x        = (const float*)d_in[0];
    const float* emb      = (const float*)d_in[2];
    const float* W_enc    = (const float*)d_in[3];
    const float* b_enc    = (const float*)d_in[4];
    const float* enc0_Wih = (const float*)d_in[5];
    const float* enc0_Whh = (const float*)d_in[6];
    const float* enc0_bih = (const float*)d_in[7];
    const float* enc0_bhh = (const float*)d_in[8];
    const float* enc1_Wih = (const float*)d_in[9];
    const float* enc1_Whh = (const float*)d_in[10];
    const float* enc1_bih = (const float*)d_in[11];
    const float* enc1_bhh = (const float*)d_in[12];
    const float* W_bi     = (const float*)d_in[13];
    const float* b_bi     = (const float*)d_in[14];
    const float* dec_Wih  = (const float*)d_in[15];
    const float* dec_Whh  = (const float*)d_in[16];
    const float* dec_bih  = (const float*)d_in[17];
    const float* dec_bhh  = (const float*)d_in[18];
    const float* W_att    = (const float*)d_in[19];
    const float* b_att    = (const float*)d_in[20];
    const float* W_out    = (const float*)d_in[21];
    const float* b_out    = (const float*)d_in[22];

    float* out_vec  = (float*)d_out;
    float* out_h    = out_vec + (size_t)Bq*LTq*Vq;
    float* out_attn = out_h + (size_t)NLq*Bq*Hq;

    cudaFuncSetAttribute(k_enc_mma, cudaFuncAttributeMaxDynamicSharedMemorySize, ENC_SMEM);
    cudaFuncSetAttribute(k_dec_pers, cudaFuncAttributeMaxDynamicSharedMemorySize, DEC_SMEM);
    cudaFuncSetAttribute(k_gemm_mma, cudaFuncAttributeMaxDynamicSharedMemorySize, GEMM_SMEM);

    __nv_bfloat16 *xr_h, *xr_l, *y0_h, *y0_l, *y1_h, *y1_l, *w0_h, *w0_l, *w1_h, *w1_l, *wb_h, *wb_l;
    __nv_bfloat16 *dwih_h, *dwih_l, *dwhh_h, *dwhh_l, *emb_h, *emb_l;
    cudaGetSymbolAddress((void**)&xr_h, g_xr_h); cudaGetSymbolAddress((void**)&xr_l, g_xr_l);
    cudaGetSymbolAddress((void**)&y0_h, g_y0_h); cudaGetSymbolAddress((void**)&y0_l, g_y0_l);
    cudaGetSymbolAddress((void**)&y1_h, g_y1_h); cudaGetSymbolAddress((void**)&y1_l, g_y1_l);
    cudaGetSymbolAddress((void**)&w0_h, g_w0_h); cudaGetSymbolAddress((void**)&w0_l, g_w0_l);
    cudaGetSymbolAddress((void**)&w1_h, g_w1_h); cudaGetSymbolAddress((void**)&w1_l, g_w1_l);
    cudaGetSymbolAddress((void**)&wb_h, g_wb_h); cudaGetSymbolAddress((void**)&wb_l, g_wb_l);
    cudaGetSymbolAddress((void**)&dwih_h, g_dwih_h); cudaGetSymbolAddress((void**)&dwih_l, g_dwih_l);
    cudaGetSymbolAddress((void**)&dwhh_h, g_dwhh_h); cudaGetSymbolAddress((void**)&dwhh_l, g_dwhh_l);
    cudaGetSymbolAddress((void**)&emb_h, g_emb_h); cudaGetSymbolAddress((void**)&emb_l, g_emb_l);
    float* gi_f; cudaGetSymbolAddress((void**)&gi_f, g_gi);
    float* v_f;  cudaGetSymbolAddress((void**)&v_f,  g_v);

    k_proj<<<(Mq*Hq + 255)/256, 256>>>(x, W_enc, b_enc);                            // 0
    k_cvt<<<(2*H3q*Hq/4 + 255)/256, 256>>>(enc0_Wih, w0_h, w0_l, 2*H3q*Hq/4);       // 1
    k_gemm_mma<<<dim3(H3q/128, Mq/128, 2), 256, GEMM_SMEM>>>(                        // 2
        xr_h, xr_l, w0_h, w0_l, enc0_bih, gi_f,
        Hq, H3q, (size_t)H3q*Hq, H3q, (size_t)Mq*H3q);
    k_enc_mma<<<128, 256, ENC_SMEM>>>(enc0_Whh, enc0_bhh, 0);                        // 3 <- profiled
    k_cvt<<<(2*H3q*2*Hq/4 + 255)/256, 256>>>(enc1_Wih, w1_h, w1_l, 2*H3q*2*Hq/4);
    k_cvt<<<(Hq*2*Hq/4 + 255)/256, 256>>>(W_bi, wb_h, wb_l, Hq*2*Hq/4);
    k_cvt<<<(NLq*H3q*Hq/4 + 255)/256, 256>>>(dec_Wih, dwih_h, dwih_l, NLq*H3q*Hq/4);
    k_cvt<<<(NLq*H3q*Hq/4 + 255)/256, 256>>>(dec_Whh, dwhh_h, dwhh_l, NLq*H3q*Hq/4);
    k_cvt<<<(Vq*Hq/4 + 255)/256, 256>>>(emb, emb_h, emb_l, Vq*Hq/4);

    // layer 1
    k_gemm_mma<<<dim3(H3q/128, Mq/128, 2), 256, GEMM_SMEM>>>(
        y0_h, y0_l, w1_h, w1_l, enc1_bih, gi_f,
        2*Hq, H3q, (size_t)H3q*2*Hq, H3q, (size_t)Mq*H3q);
    k_enc_mma<<<128, 256, ENC_SMEM>>>(enc1_Whh, enc1_bhh, 1);

    // bi_fc + norms
    k_gemm_mma<<<dim3(Hq/128, Mq/128, 1), 256, GEMM_SMEM>>>(
        y1_h, y1_l, wb_h, wb_l, b_bi, v_f,
        2*Hq, Hq, 0, 0, 0);
    k_vn<<<Mq, 128>>>();

    // persistent decoder
    k_initdec<<<(Bq*Hq + 255)/256, 256>>>();
    k_dec_pers<<<128, 256, DEC_SMEM>>>(dec_bih, dec_bhh, W_att, b_att,
                                       W_out, b_out, out_vec, out_attn);
    k_hfinal<<<(NLq*Bq*Hq + 255)/256, 256>>>(out_h);
    (void)in_sizes; (void)n_in; (void)out_size;
}

// round 16
// speedup vs baseline: 1.0452x; 1.0452x over previous
#include <cuda_runtime.h>
#include <cuda_bf16.h>
#include <math.h>
#include <stdint.h>

#define Bq 128
#define Hq 512
#define LCq 256
#define LTq 64
#define Vq 27
#define NLq 2
#define H3q (3*Hq)
#define KT 32
#define Mq (LCq*Bq)

// ---------------- scratch ----------------
__device__ float g_gi[(size_t)2*Mq*H3q];
__device__ float g_y0[(size_t)Mq*2*Hq];
__device__ float g_y1[(size_t)Mq*2*Hq];
__device__ float g_v [(size_t)Mq*Hq];
__device__ float g_vn[Mq];
__device__ float g_hd[2][NLq][Bq*Hq];
__device__ float g_a [Bq*Hq];
__device__ float g_hid[Bq*Hq];
__device__ int   g_vecin[Bq];
__device__ unsigned g_barc[2][4*32];
__device__ unsigned g_dbar[4*32];

// bf16 hi/lo decompositions
__device__ __nv_bfloat16 g_xr_h[(size_t)Mq*Hq],   g_xr_l[(size_t)Mq*Hq];
__device__ __nv_bfloat16 g_y0_h[(size_t)Mq*2*Hq], g_y0_l[(size_t)Mq*2*Hq];
__device__ __nv_bfloat16 g_y1_h[(size_t)Mq*2*Hq], g_y1_l[(size_t)Mq*2*Hq];
__device__ __nv_bfloat16 g_w0_h[2*H3q*Hq],   g_w0_l[2*H3q*Hq];
__device__ __nv_bfloat16 g_w1_h[2*H3q*2*Hq], g_w1_l[2*H3q*2*Hq];
__device__ __nv_bfloat16 g_wb_h[Hq*2*Hq],    g_wb_l[Hq*2*Hq];
// decoder bf16
__device__ __nv_bfloat16 g_dwih_h[NLq*H3q*Hq], g_dwih_l[NLq*H3q*Hq];
__device__ __nv_bfloat16 g_dwhh_h[NLq*H3q*Hq], g_dwhh_l[NLq*H3q*Hq];
__device__ __nv_bfloat16 g_emb_h[Vq*Hq], g_emb_l[Vq*Hq];
__device__ __nv_bfloat16 g_hdh[2][NLq][Bq*Hq], g_hdl[2][NLq][Bq*Hq];

// ---------------- warp-mma primitives ----------------
__device__ __forceinline__ uint32_t smem_u32(const void* p) {
    uint32_t a;
    asm("{ .reg .u64 t; cvta.to.shared.u64 t, %1; cvt.u32.u64 %0, t; }" : "=r"(a) : "l"(p));
    return a;
}
__device__ __forceinline__ void ldsm4(uint32_t& r0, uint32_t& r1, uint32_t& r2, uint32_t& r3,
                                      uint32_t a) {
    asm volatile("ldmatrix.sync.aligned.m8n8.x4.shared.b16 {%0,%1,%2,%3}, [%4];"
        : "=r"(r0), "=r"(r1), "=r"(r2), "=r"(r3) : "r"(a));
}
__device__ __forceinline__ void ldsm2(uint32_t& r0, uint32_t& r1, uint32_t a) {
    asm volatile("ldmatrix.sync.aligned.m8n8.x2.shared.b16 {%0,%1}, [%2];"
        : "=r"(r0), "=r"(r1) : "r"(a));
}
__device__ __forceinline__ void mma_bf16(float* c, const uint32_t* a, const uint32_t* b) {
    asm volatile("mma.sync.aligned.m16n8k16.row.col.f32.bf16.bf16.f32 "
        "{%0,%1,%2,%3}, {%4,%5,%6,%7}, {%8,%9}, {%0,%1,%2,%3};"
        : "+f"(c[0]), "+f"(c[1]), "+f"(c[2]), "+f"(c[3])
        : "r"(a[0]), "r"(a[1]), "r"(a[2]), "r"(a[3]), "r"(b[0]), "r"(b[1]));
}
__device__ __forceinline__ void cpa16(uint32_t s, const void* g) {
    asm volatile("cp.async.ca.shared.global [%0], [%1], 16;" :: "r"(s), "l"(g));
}
#define CP_COMMIT()  asm volatile("cp.async.commit_group;" ::: "memory")
#define CP_WAIT_1()  asm volatile("cp.async.wait_group 1;" ::: "memory")
#define CP_WAIT_0()  asm volatile("cp.async.wait_group 0;" ::: "memory")

// ---------------- fp32 -> bf16 hi/lo split ----------------
__global__ void k_cvt(const float* __restrict__ s, __nv_bfloat16* __restrict__ hi,
                      __nv_bfloat16* __restrict__ lo, int n4) {
    int i = blockIdx.x * blockDim.x + threadIdx.x;
    if (i >= n4) return;
    float4 v = *(const float4*)(s + (size_t)i*4);
    __nv_bfloat16 h0 = __float2bfloat16(v.x), h1 = __float2bfloat16(v.y);
    __nv_bfloat16 h2 = __float2bfloat16(v.z), h3 = __float2bfloat16(v.w);
    __nv_bfloat162 hA, hB, lA, lB;
    hA.x = h0; hA.y = h1; hB.x = h2; hB.y = h3;
    lA.x = __float2bfloat16(v.x - __bfloat162float(h0));
    lA.y = __float2bfloat16(v.y - __bfloat162float(h1));
    lB.x = __float2bfloat16(v.z - __bfloat162float(h2));
    lB.y = __float2bfloat16(v.w - __bfloat162float(h3));
    *(__nv_bfloat162*)(hi + (size_t)i*4)     = hA;
    *(__nv_bfloat162*)(hi + (size_t)i*4 + 2) = hB;
    *(__nv_bfloat162*)(lo + (size_t)i*4)     = lA;
    *(__nv_bfloat162*)(lo + (size_t)i*4 + 2) = lB;
}

// ---------------- encoder input projection (fused hi/lo + barrier reset) -------
__global__ void k_proj(const float* __restrict__ x, const float* __restrict__ W_enc,
                       const float* __restrict__ b_enc) {
    int idx = blockIdx.x * blockDim.x + threadIdx.x;
    if (blockIdx.x == 0 && threadIdx.x == 0) {
        for (int i = 0; i < 2; i++)
            for (int j = 0; j < 4; j++) g_barc[i][j*32] = 0;
        for (int j = 0; j < 4; j++) g_dbar[j*32] = 0;
    }
    if (idx >= Mq*Hq) return;
    int h = idx % Hq; int bl = idx / Hq; int b = bl % Bq; int l = bl / Bq;
    float v = x[(size_t)b*2*LCq + l] * W_enc[h*2]
            + x[(size_t)b*2*LCq + LCq + l] * W_enc[h*2+1] + b_enc[h];
    __nv_bfloat16 hv = __float2bfloat16(v);
    g_xr_h[idx] = hv;
    g_xr_l[idx] = __float2bfloat16(v - __bfloat162float(hv));
}

// ---------------- tensor-core GEMM: CTA 128x128, warp 32x64, cp.async ---------
#define AROW 40
#define GT (128*AROW)
#define GEMM_SMEM (8*GT*2)
__global__ void __launch_bounds__(256) k_gemm_mma(
        const __nv_bfloat16* __restrict__ Ah, const __nv_bfloat16* __restrict__ Al,
        const __nv_bfloat16* __restrict__ Wh, const __nv_bfloat16* __restrict__ Wl,
        const float* __restrict__ bias, float* __restrict__ C,
        int K, int Nld, size_t wStrideZ, int bStrideZ, size_t cStrideZ) {
    extern __shared__ __nv_bfloat16 gsm[];
    __nv_bfloat16* sAh = gsm;
    __nv_bfloat16* sAl = gsm + 2*GT;
    __nv_bfloat16* sWh = gsm + 4*GT;
    __nv_bfloat16* sWl = gsm + 6*GT;

    int tid = threadIdx.x, wid = tid >> 5, lane = tid & 31;
    int z = blockIdx.z;
    const __nv_bfloat16* Whz = Wh + (size_t)z*wStrideZ;
    const __nv_bfloat16* Wlz = Wl + (size_t)z*wStrideZ;
    const float* bias_z = bias + (size_t)z*bStrideZ;
    float* C_z = C + (size_t)z*cStrideZ;
    int col0 = blockIdx.x * 128, row0 = blockIdx.y * 128;
    int wm = (wid & 3) * 32, wn = (wid >> 2) * 64;

    float acc[2][8][4];
    #pragma unroll
    for (int i = 0; i < 2; i++)
        #pragma unroll
        for (int j = 0; j < 8; j++)
            #pragma unroll
            for (int k = 0; k < 4; k++) acc[i][j][k] = 0.f;

    uint32_t aBase = smem_u32(sAh), alBase = smem_u32(sAl);
    uint32_t wBase = smem_u32(sWh), wlBase = smem_u32(sWl);
    int aRow = wm + (lane & 15);
    int aCol = (lane >> 4) * 8;
    int g = lane >> 3;
    int bRow = wn + (lane & 7) + ((g >> 1) & 1) * 8;
    int bCol = (g & 1) * 8;

    int r0 = tid >> 2, c0 = tid & 3;
    int r1 = (tid + 256) >> 2, c1 = (tid + 256) & 3;
    uint32_t sOff0 = (uint32_t)((r0*AROW + c0*8) * 2);
    uint32_t sOff1 = (uint32_t)((r1*AROW + c1*8) * 2);
    size_t goA0 = (size_t)(row0 + r0)*K + c0*8;
    size_t goA1 = (size_t)(row0 + r1)*K + c1*8;
    size_t goW0 = (size_t)(col0 + r0)*K + c0*8;
    size_t goW1 = (size_t)(col0 + r1)*K + c1*8;

    int nk = K >> 5;
    {
        cpa16(aBase  + sOff0, Ah + goA0);  cpa16(aBase  + sOff1, Ah + goA1);
        cpa16(alBase + sOff0, Al + goA0);  cpa16(alBase + sOff1, Al + goA1);
        cpa16(wBase  + sOff0, Whz + goW0); cpa16(wBase  + sOff1, Whz + goW1);
        cpa16(wlBase + sOff0, Wlz + goW0); cpa16(wlBase + sOff1, Wlz + goW1);
        CP_COMMIT();
    }
    int buf = 0;
    for (int kc = 0; kc < nk; kc++) {
        if (kc + 1 < nk) {
            int kn = (kc + 1) << 5;
            uint32_t bo = (uint32_t)((buf ^ 1) * GT * 2);
            cpa16(aBase  + bo + sOff0, Ah + goA0 + kn);  cpa16(aBase  + bo + sOff1, Ah + goA1 + kn);
            cpa16(alBase + bo + sOff0, Al + goA0 + kn);  cpa16(alBase + bo + sOff1, Al + goA1 + kn);
            cpa16(wBase  + bo + sOff0, Whz + goW0 + kn); cpa16(wBase  + bo + sOff1, Whz + goW1 + kn);
            cpa16(wlBase + bo + sOff0, Wlz + goW0 + kn); cpa16(wlBase + bo + sOff1, Wlz + goW1 + kn);
            CP_COMMIT();
            CP_WAIT_1();
        } else {
            CP_WAIT_0();
        }
        __syncthreads();

        uint32_t abH = aBase  + (uint32_t)(buf*GT*2);
        uint32_t abL = alBase + (uint32_t)(buf*GT*2);
        uint32_t wbH = wBase  + (uint32_t)(buf*GT*2);
        uint32_t wbL = wlBase + (uint32_t)(buf*GT*2);

        #pragma unroll
        for (int ks = 0; ks < 2; ks++) {
            uint32_t ah[2][4], al[2][4];
            #pragma unroll
            for (int mi = 0; mi < 2; mi++) {
                uint32_t off = (uint32_t)(((aRow + mi*16)*AROW + ks*16 + aCol) * 2);
                ldsm4(ah[mi][0], ah[mi][1], ah[mi][2], ah[mi][3], abH + off);
                ldsm4(al[mi][0], al[mi][1], al[mi][2], al[mi][3], abL + off);
            }
            #pragma unroll
            for (int ng = 0; ng < 4; ng++) {
                uint32_t bh[4], bl[4];
                uint32_t off = (uint32_t)(((bRow + ng*16)*AROW + ks*16 + bCol) * 2);
                ldsm4(bh[0], bh[1], bh[2], bh[3], wbH + off);
                ldsm4(bl[0], bl[1], bl[2], bl[3], wbL + off);
                #pragma unroll
                for (int mi = 0; mi < 2; mi++)
                    #pragma unroll
                    for (int half = 0; half < 2; half++) {
                        float* c = acc[mi][ng*2 + half];
                        mma_bf16(c, ah[mi], &bh[half*2]);
                        mma_bf16(c, ah[mi], &bl[half*2]);
                        mma_bf16(c, al[mi], &bh[half*2]);
                    }
            }
        }
        __syncthreads();
        buf ^= 1;
    }

    #pragma unroll
    for (int mi = 0; mi < 2; mi++) {
        int r_ = row0 + wm + mi*16 + (lane >> 2);
        #pragma unroll
        for (int ni = 0; ni < 8; ni++) {
            int c_ = col0 + wn + ni*8 + (lane & 3)*2;
            float b0 = bias_z[c_], b1 = bias_z[c_ + 1];
            float2 o0 = { acc[mi][ni][0] + b0, acc[mi][ni][1] + b1 };
            float2 o1 = { acc[mi][ni][2] + b0, acc[mi][ni][3] + b1 };
            *(float2*)(C_z + (size_t)r_*Nld + c_)       = o0;
            *(float2*)(C_z + (size_t)(r_ + 8)*Nld + c_) = o1;
        }
    }
}

// ---------------- persistent MMA encoder GRU layer (R11 winner) ----------------
#define WP 520
#define AP 136
#define ENC_SMEM ((96*WP + 4*64*AP) * 2)
__global__ void __launch_bounds__(256, 1) k_enc_mma(
        const float* __restrict__ Whh2, const float* __restrict__ bhh2, int layer) {
    extern __shared__ __nv_bfloat16 smb[];
    __nv_bfloat16* sWh = smb;
    __nv_bfloat16* sWl = smb + 48*WP;
    __nv_bfloat16* sAh = smb + 96*WP;
    __nv_bfloat16* sAl = smb + 96*WP + 2*64*AP;

    float* Y = layer ? g_y1 : g_y0;
    __nv_bfloat16* Yh = layer ? g_y1_h : g_y0_h;
    __nv_bfloat16* Yl = layer ? g_y1_l : g_y0_l;

    int bid = blockIdx.x;
    int dirv = bid >> 6;
    int rem = bid & 63;
    int cg = rem & 31;
    int bg = rem >> 5;
    int gc0 = cg * 16;
    int row0 = bg * 64;
    unsigned grp = ((unsigned)dirv << 1) | (unsigned)bg;

    int tid = threadIdx.x, wid = tid >> 5, lane = tid & 31;
    int wm = (wid & 3) * 16;
    int ws = wid >> 2;

    const float* Whh = Whh2 + (size_t)dirv*H3q*Hq;
    const float* bhh = bhh2 + dirv*H3q;

    for (int u = tid; u < 48*128; u += 256) {
        int rrow = u >> 7, kq = u & 127;
        int g = rrow >> 4, c = rrow & 15;
        float4 w = __ldg((const float4*)(Whh + (size_t)(g*Hq + gc0 + c)*Hq) + kq);
        __nv_bfloat16 h0 = __float2bfloat16(w.x), h1 = __float2bfloat16(w.y);
        __nv_bfloat16 h2 = __float2bfloat16(w.z), h3 = __float2bfloat16(w.w);
        __nv_bfloat162 hh0; hh0.x = h0; hh0.y = h1;
        __nv_bfloat162 hh1; hh1.x = h2; hh1.y = h3;
        __nv_bfloat162 ll0, ll1;
        ll0.x = __float2bfloat16(w.x - __bfloat162float(h0));
        ll0.y = __float2bfloat16(w.y - __bfloat162float(h1));
        ll1.x = __float2bfloat16(w.z - __bfloat162float(h2));
        ll1.y = __float2bfloat16(w.w - __bfloat162float(h3));
        *(__nv_bfloat162*)(sWh + rrow*WP + kq*4)     = hh0;
        *(__nv_bfloat162*)(sWh + rrow*WP + kq*4 + 2) = hh1;
        *(__nv_bfloat162*)(sWl + rrow*WP + kq*4)     = ll0;
        *(__nv_bfloat162*)(sWl + rrow*WP + kq*4 + 2) = ll1;
    }
    int cA = gc0 + ws*8 + 2*(lane & 3);
    float br0 = __ldg(bhh + cA),        br1 = __ldg(bhh + cA + 1);
    float bz0 = __ldg(bhh + 512 + cA),  bz1 = __ldg(bhh + 512 + cA + 1);
    float bn0 = __ldg(bhh + 1024 + cA), bn1 = __ldg(bhh + 1024 + cA + 1);
    __syncthreads();

    uint32_t aBaseH = smem_u32(sAh), aBaseL = smem_u32(sAl);
    uint32_t wBaseH = smem_u32(sWh), wBaseL = smem_u32(sWl);
    uint32_t aOff = (uint32_t)(((wm + (lane & 15))*AP + (lane >> 4)*8) * 2);
    int bRow = ws*8 + (lane & 7);
    uint32_t bColOff = (uint32_t)((((lane >> 3) & 1) * 8) * 2);

    int sr[4], sc[4];
    #pragma unroll
    for (int i = 0; i < 4; i++) {
        int slot = tid + i*256;
        sr[i] = slot >> 4; sc[i] = slot & 15;
    }

    float2 hpreg[2];
    hpreg[0] = make_float2(0.f, 0.f);
    hpreg[1] = make_float2(0.f, 0.f);

    for (int s = 0; s < LCq; s++) {
        int t = dirv ? (LCq-1-s) : s;
        int tprev = dirv ? (t+1) : (t-1);

        const float* gi_t = g_gi + ((size_t)dirv*LCq + t)*Bq*H3q;
        float2 gr[2], gz[2], gn[2];
        #pragma unroll
        for (int rr = 0; rr < 2; rr++) {
            int b = row0 + wm + (lane >> 2) + rr*8;
            const float* gib = gi_t + (size_t)b*H3q;
            gr[rr] = __ldg((const float2*)(gib + cA));
            gz[rr] = __ldg((const float2*)(gib + 512 + cA));
            gn[rr] = __ldg((const float2*)(gib + 1024 + cA));
        }

        float acc[3][4];
        #pragma unroll
        for (int g = 0; g < 3; g++) {
            acc[g][0] = acc[g][1] = acc[g][2] = acc[g][3] = 0.f;
        }

        if (s > 0) {
            const __nv_bfloat16* Ahp = Yh + ((size_t)tprev*Bq)*2*Hq + (size_t)dirv*Hq;
            const __nv_bfloat16* Alp = Yl + ((size_t)tprev*Bq)*2*Hq + (size_t)dirv*Hq;
            uint4 ph[4], pl[4];
            #pragma unroll
            for (int i = 0; i < 4; i++) {
                ph[i] = __ldcg((const uint4*)(Ahp + (size_t)(row0 + sr[i])*2*Hq + sc[i]*8));
                pl[i] = __ldcg((const uint4*)(Alp + (size_t)(row0 + sr[i])*2*Hq + sc[i]*8));
            }
            int buf = 0;
            for (int kc = 0; kc < 4; kc++) {
                __nv_bfloat16* dAh = sAh + buf*64*AP;
                __nv_bfloat16* dAl = sAl + buf*64*AP;
                #pragma unroll
                for (int i = 0; i < 4; i++) {
                    *(uint4*)(dAh + sr[i]*AP + sc[i]*8) = ph[i];
                    *(uint4*)(dAl + sr[i]*AP + sc[i]*8) = pl[i];
                }
                __syncthreads();
                if (kc < 3) {
                    int k1 = (kc + 1)*128;
                    #pragma unroll
                    for (int i = 0; i < 4; i++) {
                        ph[i] = __ldcg((const uint4*)(Ahp + (size_t)(row0 + sr[i])*2*Hq + k1 + sc[i]*8));
                        pl[i] = __ldcg((const uint4*)(Alp + (size_t)(row0 + sr[i])*2*Hq + k1 + sc[i]*8));
                    }
                }
                int k0 = kc*128;
                uint32_t abH = aBaseH + (uint32_t)(buf*64*AP*2);
                uint32_t abL = aBaseL + (uint32_t)(buf*64*AP*2);
                #pragma unroll
                for (int ks = 0; ks < 8; ks++) {
                    uint32_t ah[4], al[4];
                    uint32_t ao = aOff + (uint32_t)(ks*32);
                    ldsm4(ah[0], ah[1], ah[2], ah[3], abH + ao);
                    ldsm4(al[0], al[1], al[2], al[3], abL + ao);
                    #pragma unroll
                    for (int g = 0; g < 3; g++) {
                        uint32_t bh[2], bl[2];
                        uint32_t wo = (uint32_t)((((g*16 + bRow)*WP) + k0 + ks*16)*2) + bColOff;
                        ldsm2(bh[0], bh[1], wBaseH + wo);
                        ldsm2(bl[0], bl[1], wBaseL + wo);
                        mma_bf16(acc[g], ah, bh);
                        mma_bf16(acc[g], ah, bl);
                        mma_bf16(acc[g], al, bh);
                    }
                }
                __syncthreads();
                buf ^= 1;
            }
        }

        #pragma unroll
        for (int rr = 0; rr < 2; rr++) {
            int b = row0 + wm + (lane >> 2) + rr*8;
            float r0v = 1.f/(1.f + expf(-(gr[rr].x + acc[0][rr*2]   + br0)));
            float r1v = 1.f/(1.f + expf(-(gr[rr].y + acc[0][rr*2+1] + br1)));
            float z0v = 1.f/(1.f + expf(-(gz[rr].x + acc[1][rr*2]   + bz0)));
            float z1v = 1.f/(1.f + expf(-(gz[rr].y + acc[1][rr*2+1] + bz1)));
            float n0v = tanhf(gn[rr].x + r0v*(acc[2][rr*2]   + bn0));
            float n1v = tanhf(gn[rr].y + r1v*(acc[2][rr*2+1] + bn1));
            float h0v = (1.f - z0v)*n0v + z0v*hpreg[rr].x;
            float h1v = (1.f - z1v)*n1v + z1v*hpreg[rr].y;
            hpreg[rr] = make_float2(h0v, h1v);
            size_t o = ((size_t)t*Bq + b)*2*Hq + (size_t)dirv*Hq + cA;
            if (layer == 0 && s == LCq-1)
                *(float2*)(Y + o) = hpreg[rr];
            __nv_bfloat16 bh0 = __float2bfloat16(h0v), bh1 = __float2bfloat16(h1v);
            __nv_bfloat162 hv; hv.x = bh0; hv.y = bh1;
            __nv_bfloat162 lv;
            lv.x = __float2bfloat16(h0v - __bfloat162float(bh0));
            lv.y = __float2bfloat16(h1v - __bfloat162float(bh1));
            *(__nv_bfloat162*)(Yh + o) = hv;
            *(__nv_bfloat162*)(Yl + o) = lv;
        }

        __threadfence();
        __syncthreads();
        if (tid == 0) {
            atomicAdd(&g_barc[layer][grp*32], 1u);
            unsigned target = 32u * (unsigned)(s + 1);
            while (*(volatile unsigned*)&g_barc[layer][grp*32] < target) { }
        }
        __syncthreads();
    }
}

// ---------------- v row norms ----------------
__global__ void k_vn() {
    int row = blockIdx.x;
    int tid = threadIdx.x;
    const float* vr = g_v + (size_t)row*Hq;
    float s = 0.f;
    for (int k = tid; k < Hq; k += 128) { float x = vr[k]; s = fmaf(x, x, s); }
    __shared__ float red[128];
    red[tid] = s; __syncthreads();
    for (int o = 64; o > 0; o >>= 1) { if (tid < o) red[tid] += red[tid + o]; __syncthreads(); }
    if (tid == 0) g_vn[row] = fmaxf(sqrtf(red[0]), 1e-8f);
}

// ---------------- decoder init (fp32 + hi/lo) ----------------
__global__ void k_initdec() {
    int idx = blockIdx.x * blockDim.x + threadIdx.x;
    if (idx < Bq) g_vecin[idx] = 0;
    if (idx < Bq*Hq) {
        int b = idx / Hq, h = idx % Hq;
        float h0 = g_y0[((size_t)(LCq-1)*Bq + b)*2*Hq + h];
        float h1 = g_y0[((size_t)b)*2*Hq + Hq + h];
        g_hd[0][0][idx] = h0;
        g_hd[0][1][idx] = h1;
        __nv_bfloat16 a = __float2bfloat16(h0);
        __nv_bfloat16 c = __float2bfloat16(h1);
        g_hdh[0][0][idx] = a;
        g_hdl[0][0][idx] = __float2bfloat16(h0 - __bfloat162float(a));
        g_hdh[0][1][idx] = c;
        g_hdl[0][1][idx] = __float2bfloat16(h1 - __bfloat162float(c));
    }
}

// ================= persistent decoder =================
#define DEC_SMEM 55296

// group-local barrier: the 4 bg-groups are fully independent decoders
__device__ __forceinline__ void dec_gridbar(unsigned seq) {
    __threadfence();
    __syncthreads();
    if (threadIdx.x == 0) {
        unsigned grp = blockIdx.x >> 5;
        atomicAdd(&g_dbar[grp*32], 1u);
        unsigned t = 32u * seq;
        while (*(volatile unsigned*)&g_dbar[grp*32] < t) { }
    }
    __syncthreads();
}

__device__ void dec_gru_stage(char* sm, int l, int p, float* hreg,
        const __nv_bfloat16* __restrict__ Wih_h, const __nv_bfloat16* __restrict__ Wih_l,
        const __nv_bfloat16* __restrict__ Whh_h, const __nv_bfloat16* __restrict__ Whh_l,
        const float* __restrict__ bih, const float* __restrict__ bhh) {
    __nv_bfloat16* sWh = (__nv_bfloat16*)sm;
    __nv_bfloat16* sWl = sWh + 96*72;
    __nv_bfloat16* sXh = sWl + 96*72;
    __nv_bfloat16* sXl = sXh + 32*72;
    __nv_bfloat16* sHh = sXl + 32*72;
    __nv_bfloat16* sHl = sHh + 32*72;
    float* sAcc = (float*)(sHl + 32*72);
    int* vs = (int*)(sAcc + 4*32*17);

    int tid = threadIdx.x, lane = tid & 31, wid = tid >> 5;
    int cg = blockIdx.x & 31, bg = blockIdx.x >> 5;
    int gc0 = cg * 16, row0 = bg * 32;
    int wm16 = (wid & 1) * 16;
    int wq = wid >> 1;

    if (l == 0 && tid < 32) vs[tid] = __ldcg(&g_vecin[row0 + tid]);

    const __nv_bfloat16* Hh = g_hdh[p][l];
    const __nv_bfloat16* Hl = g_hdl[p][l];
    const __nv_bfloat16* Xh_g = (l == 0) ? g_emb_h : g_hdh[1-p][0];
    const __nv_bfloat16* Xl_g = (l == 0) ? g_emb_l : g_hdl[1-p][0];

    float acc[2][4] = {{0,0,0,0},{0,0,0,0}};

    uint32_t aXh = smem_u32(sXh), aXl = smem_u32(sXl);
    uint32_t aHh = smem_u32(sHh), aHl = smem_u32(sHl);
    uint32_t wBh = smem_u32(sWh), wBl = smem_u32(sWl);
    uint32_t aOffBase = (uint32_t)(((wm16 + (lane & 15))*72 + (lane >> 4)*8) * 2);
    int bRowIn = (lane & 7) + ((lane >> 4) & 1)*8;
    uint32_t bColOff = (uint32_t)((((lane >> 3) & 1) * 8) * 2);

    __syncthreads();

    for (int kc = 0; kc < 8; kc++) {
        int k0 = kc * 64;
        #pragma unroll
        for (int i = 0; i < 3; i++) {
            int u = tid + i*256;
            int rr = u >> 3, ku = u & 7;
            int grow = rr < 48 ? rr : rr - 48;
            int g = grow >> 4, c = grow & 15;
            size_t src = (size_t)(g*Hq + gc0 + c)*Hq + k0 + ku*8;
            const __nv_bfloat16* MH = rr < 48 ? Wih_h : Whh_h;
            const __nv_bfloat16* ML = rr < 48 ? Wih_l : Whh_l;
            *(uint4*)(sWh + rr*72 + ku*8) = *(const uint4*)(MH + src);
            *(uint4*)(sWl + rr*72 + ku*8) = *(const uint4*)(ML + src);
        }
        {
            int rr = tid >> 3, ku = tid & 7;
            size_t xoff;
            if (l == 0) xoff = (size_t)vs[rr]*Hq + k0 + ku*8;
            else        xoff = (size_t)(row0 + rr)*Hq + k0 + ku*8;
            if (l == 0) {
                *(uint4*)(sXh + rr*72 + ku*8) = *(const uint4*)(Xh_g + xoff);
                *(uint4*)(sXl + rr*72 + ku*8) = *(const uint4*)(Xl_g + xoff);
            } else {
                *(uint4*)(sXh + rr*72 + ku*8) = __ldcg((const uint4*)(Xh_g + xoff));
                *(uint4*)(sXl + rr*72 + ku*8) = __ldcg((const uint4*)(Xl_g + xoff));
            }
            size_t hoff = (size_t)(row0 + rr)*Hq + k0 + ku*8;
            *(uint4*)(sHh + rr*72 + ku*8) = __ldcg((const uint4*)(Hh + hoff));
            *(uint4*)(sHl + rr*72 + ku*8) = __ldcg((const uint4*)(Hl + hoff));
        }
        __syncthreads();

        #pragma unroll
        for (int ks = 0; ks < 4; ks++) {
            uint32_t ao = aOffBase + (uint32_t)(ks*32);
            uint32_t coff = bColOff + (uint32_t)(ks*32);
            if (wq < 2) {
                uint32_t axh[4], axl[4], ahh[4], ahl[4];
                ldsm4(axh[0], axh[1], axh[2], axh[3], aXh + ao);
                ldsm4(axl[0], axl[1], axl[2], axl[3], aXl + ao);
                ldsm4(ahh[0], ahh[1], ahh[2], ahh[3], aHh + ao);
                ldsm4(ahl[0], ahl[1], ahl[2], ahl[3], aHl + ao);
                int gih = wq*16, ghh = 48 + wq*16;
                uint32_t bih_h[4], bih_l[4], bhh_h[4], bhh_l[4];
                uint32_t oi = (uint32_t)(((gih + bRowIn)*72)*2) + coff;
                uint32_t oh = (uint32_t)(((ghh + bRowIn)*72)*2) + coff;
                ldsm4(bih_h[0], bih_h[1], bih_h[2], bih_h[3], wBh + oi);
                ldsm4(bih_l[0], bih_l[1], bih_l[2], bih_l[3], wBl + oi);
                ldsm4(bhh_h[0], bhh_h[1], bhh_h[2], bhh_h[3], wBh + oh);
                ldsm4(bhh_l[0], bhh_l[1], bhh_l[2], bhh_l[3], wBl + oh);
                #pragma unroll
                for (int ni = 0; ni < 2; ni++) {
                    mma_bf16(acc[ni], axh, &bih_h[ni*2]);
                    mma_bf16(acc[ni], axh, &bih_l[ni*2]);
                    mma_bf16(acc[ni], axl, &bih_h[ni*2]);
                    mma_bf16(acc[ni], ahh, &bhh_h[ni*2]);
                    mma_bf16(acc[ni], ahh, &bhh_l[ni*2]);
                    mma_bf16(acc[ni], ahl, &bhh_h[ni*2]);
                }
            } else if (wq == 2) {
                uint32_t axh[4], axl[4], bh[4], bl[4];
                ldsm4(axh[0], axh[1], axh[2], axh[3], aXh + ao);
                ldsm4(axl[0], axl[1], axl[2], axl[3], aXl + ao);
                uint32_t oi = (uint32_t)(((32 + bRowIn)*72)*2) + coff;
                ldsm4(bh[0], bh[1], bh[2], bh[3], wBh + oi);
                ldsm4(bl[0], bl[1], bl[2], bl[3], wBl + oi);
                #pragma unroll
                for (int ni = 0; ni < 2; ni++) {
                    mma_bf16(acc[ni], axh, &bh[ni*2]);
                    mma_bf16(acc[ni], axh, &bl[ni*2]);
                    mma_bf16(acc[ni], axl, &bh[ni*2]);
                }
            } else {
                uint32_t ahh[4], ahl[4], bh[4], bl[4];
                ldsm4(ahh[0], ahh[1], ahh[2], ahh[3], aHh + ao);
                ldsm4(ahl[0], ahl[1], ahl[2], ahl[3], aHl + ao);
                uint32_t oh = (uint32_t)(((80 + bRowIn)*72)*2) + coff;
                ldsm4(bh[0], bh[1], bh[2], bh[3], wBh + oh);
                ldsm4(bl[0], bl[1], bl[2], bl[3], wBl + oh);
                #pragma unroll
                for (int ni = 0; ni < 2; ni++) {
                    mma_bf16(acc[ni], ahh, &bh[ni*2]);
                    mma_bf16(acc[ni], ahh, &bl[ni*2]);
                    mma_bf16(acc[ni], ahl, &bh[ni*2]);
                }
            }
        }
        __syncthreads();
    }

    {
        int r0 = wm16 + (lane >> 2);
        #pragma unroll
        for (int ni = 0; ni < 2; ni++) {
            int cb = ni*8 + (lane & 3)*2;
            sAcc[(wq*32 + r0)*17 + cb]       = acc[ni][0];
            sAcc[(wq*32 + r0)*17 + cb + 1]   = acc[ni][1];
            sAcc[(wq*32 + r0+8)*17 + cb]     = acc[ni][2];
            sAcc[(wq*32 + r0+8)*17 + cb + 1] = acc[ni][3];
        }
    }
    __syncthreads();

    #pragma unroll
    for (int j = 0; j < 2; j++) {
        int e = tid + j*256;
        int row = e >> 4, col = e & 15;
        float rv  = sAcc[(0*32 + row)*17 + col];
        float zv  = sAcc[(1*32 + row)*17 + col];
        float nxv = sAcc[(2*32 + row)*17 + col];
        float nhv = sAcc[(3*32 + row)*17 + col];
        int c = gc0 + col, b = row0 + row;
        float rr = 1.f/(1.f + expf(-(rv + __ldg(bih + c) + __ldg(bhh + c))));
        float zz = 1.f/(1.f + expf(-(zv + __ldg(bih + 512 + c) + __ldg(bhh + 512 + c))));
        float nn = tanhf(nxv + __ldg(bih + 1024 + c) + rr*(nhv + __ldg(bhh + 1024 + c)));
        float h = (1.f - zz)*nn + zz*hreg[j];
        hreg[j] = h;
        g_hd[1-p][l][(size_t)b*Hq + c] = h;
        __nv_bfloat16 bh = __float2bfloat16(h);
        g_hdh[1-p][l][(size_t)b*Hq + c] = bh;
        g_hdl[1-p][l][(size_t)b*Hq + c] = __float2bfloat16(h - __bfloat162float(bh));
    }
}

// single-pass attention: v kept in registers; sim in [-1,1] => constant shift 1.0
__device__ void dec_attn_stage(char* sm, int t, int p, float* __restrict__ attn_out) {
    float* qs   = (float*)sm;            // 512
    float* red  = qs + 512;              // 256
    float* se   = red + 256;             // 256
    float* pc   = se + 256;              // 8*512 partial contexts
    float* wsum = pc + 8*512;            // 8
    int b = blockIdx.x;
    int tid = threadIdx.x, wid = tid >> 5, lane = tid & 31;

    const float* q = g_hd[1-p][1] + (size_t)b*Hq;
    qs[tid]       = __ldcg(q + tid);
    qs[tid + 256] = __ldcg(q + tid + 256);
    __syncthreads();

    float ss = qs[tid]*qs[tid] + qs[tid+256]*qs[tid+256];
    red[tid] = ss; __syncthreads();
    for (int o = 128; o > 0; o >>= 1) { if (tid < o) red[tid] += red[tid + o]; __syncthreads(); }
    float qinv = 1.f / fmaxf(sqrtf(red[0]), 1e-8f);
    __syncthreads();

    // q fragment for this lane: 16 values at lane*4 + j*128
    float qf[16];
    #pragma unroll
    for (int j = 0; j < 4; j++) {
        float4 c = *(const float4*)(qs + lane*4 + j*128);
        qf[j*4+0]=c.x; qf[j*4+1]=c.y; qf[j*4+2]=c.z; qf[j*4+3]=c.w;
    }

    float acc[16];
    #pragma unroll
    for (int i = 0; i < 16; i++) acc[i] = 0.f;
    float ssum = 0.f;

    // warp wid handles rows [wid*32, wid*32+32): single pass over v
    for (int li = 0; li < 32; li++) {
        int l = wid*32 + li;
        const float* vrow = g_v + ((size_t)l*Bq + b)*Hq;
        float vf[16];
        float d = 0.f;
        #pragma unroll
        for (int j = 0; j < 4; j++) {
            float4 a = __ldcg((const float4*)(vrow + lane*4 + j*128));
            vf[j*4+0]=a.x; vf[j*4+1]=a.y; vf[j*4+2]=a.z; vf[j*4+3]=a.w;
            d = fmaf(a.x, qf[j*4+0], d); d = fmaf(a.y, qf[j*4+1], d);
            d = fmaf(a.z, qf[j*4+2], d); d = fmaf(a.w, qf[j*4+3], d);
        }
        #pragma unroll
        for (int o = 16; o > 0; o >>= 1) d += __shfl_xor_sync(0xffffffffu, d, o);
        float vn = __ldg(&g_vn[(size_t)l*Bq + b]);
        float e = expf(d * qinv / vn - 1.0f);
        if (lane == 0) se[l] = e;
        ssum += e;
        #pragma unroll
        for (int i = 0; i < 16; i++) acc[i] = fmaf(e, vf[i], acc[i]);
    }

    // write per-warp partials
    #pragma unroll
    for (int j = 0; j < 4; j++) {
        float4 o4 = make_float4(acc[j*4], acc[j*4+1], acc[j*4+2], acc[j*4+3]);
        *(float4*)(pc + wid*512 + lane*4 + j*128) = o4;
    }
    if (lane == 0) wsum[wid] = ssum;
    __syncthreads();

    float tot = wsum[0]+wsum[1]+wsum[2]+wsum[3]+wsum[4]+wsum[5]+wsum[6]+wsum[7];
    float inv = 1.f / tot;

    float a0 = 0.f, a1 = 0.f;
    #pragma unroll
    for (int w = 0; w < 8; w++) {
        a0 += pc[w*512 + tid];
        a1 += pc[w*512 + tid + 256];
    }
    g_a[(size_t)b*Hq + tid]       = a0 * inv;
    g_a[(size_t)b*Hq + tid + 256] = a1 * inv;
    attn_out[((size_t)b*LCq + tid)*LTq + t] = se[tid] * inv;
}

__device__ void dec_attfc_stage(char* sm, int p,
        const float* __restrict__ Watt, const float* __restrict__ batt) {
    float* Xs  = (float*)sm;
    float* As2 = Xs + 32*33;
    float* Wqs = As2 + 32*33;
    float* Was = Wqs + 32*17;

    const float* X1 = g_hd[1-p][1];
    const float* X2 = g_a;
    int tid = threadIdx.x;
    int tx = tid & 15, ty = tid >> 4;
    int col0 = (blockIdx.x & 31) * 16, row0 = (blockIdx.x >> 5) * 32;

    float acc[2] = {0,0};
    for (int k0 = 0; k0 < Hq; k0 += KT) {
        {
            int r = tid >> 3, kk = (tid & 7) << 2;
            float4 x4 = __ldcg((const float4*)(X1 + (size_t)(row0 + r)*Hq + k0 + kk));
            Xs[kk*33 + r]=x4.x; Xs[(kk+1)*33 + r]=x4.y; Xs[(kk+2)*33 + r]=x4.z; Xs[(kk+3)*33 + r]=x4.w;
            float4 a4 = __ldcg((const float4*)(X2 + (size_t)(row0 + r)*Hq + k0 + kk));
            As2[kk*33 + r]=a4.x; As2[(kk+1)*33 + r]=a4.y; As2[(kk+2)*33 + r]=a4.z; As2[(kk+3)*33 + r]=a4.w;
        }
        #pragma unroll
        for (int j = 0; j < 2; j++) {
            int lin = tid + j*256;
            int c = lin >> 5, k = lin & 31;
            Wqs[k*17 + c] = __ldg(Watt + (size_t)(col0 + c)*2*Hq + k0 + k);
            Was[k*17 + c] = __ldg(Watt + (size_t)(col0 + c)*2*Hq + Hq + k0 + k);
        }
        __syncthreads();
        #pragma unroll
        for (int k = 0; k < KT; k++) {
            float wq = Wqs[k*17 + tx], wa = Was[k*17 + tx];
            #pragma unroll
            for (int i = 0; i < 2; i++) {
                acc[i] = fmaf(Xs[k*33 + ty + 16*i], wq, acc[i]);
                acc[i] = fmaf(As2[k*33 + ty + 16*i], wa, acc[i]);
            }
        }
        __syncthreads();
    }
    int c = col0 + tx;
    #pragma unroll
    for (int i = 0; i < 2; i++) {
        int b = row0 + ty + 16*i;
        g_hid[(size_t)b*Hq + c] = acc[i] + __ldg(batt + c);
    }
}

__device__ void dec_out_stage(char* sm, int t,
        const float* __restrict__ Wout, const float* __restrict__ bout,
        float* __restrict__ vecout) {
    float* hs = (float*)sm;
    float* lg = hs + 512;
    int b = blockIdx.x;
    int tid = threadIdx.x;
    hs[tid]       = __ldcg(&g_hid[(size_t)b*Hq + tid]);
    hs[tid + 256] = __ldcg(&g_hid[(size_t)b*Hq + tid + 256]);
    __syncthreads();

    int wid = tid >> 5, lane = tid & 31;
    for (int j = wid; j < Vq; j += 8) {
        float acc = 0.f;
        for (int k = lane; k < Hq; k += 32)
            acc = fmaf(hs[k], __ldg(Wout + (size_t)j*Hq + k), acc);
        #pragma unroll
        for (int o = 16; o > 0; o >>= 1) acc += __shfl_down_sync(0xffffffffu, acc, o);
        if (lane == 0) lg[j] = acc + __ldg(bout + j);
    }
    __syncthreads();
    if (tid < Vq) vecout[((size_t)b*LTq + t)*Vq + tid] = lg[tid];
    if (tid == 0) {
        int best = 0; float bv = lg[0];
        for (int j = 1; j < Vq; j++) { if (lg[j] > bv) { bv = lg[j]; best = j; } }
        g_vecin[b] = best;
    }
}

__global__ void __launch_bounds__(256, 1) k_dec_pers(
        const float* __restrict__ dec_bih, const float* __restrict__ dec_bhh,
        const float* __restrict__ Watt, const float* __restrict__ batt,
        const float* __restrict__ Wout, const float* __restrict__ bout,
        float* __restrict__ vecout, float* __restrict__ attn_out) {
    extern __shared__ char dsm[];
    int tid = threadIdx.x;
    int cg = blockIdx.x & 31, bg = blockIdx.x >> 5;
    int gc0 = cg * 16, row0 = bg * 32;

    float hdreg[2][2];
    #pragma unroll
    for (int l = 0; l < 2; l++)
        #pragma unroll
        for (int j = 0; j < 2; j++) {
            int e = tid + j*256;
            int row = e >> 4, col = e & 15;
            hdreg[l][j] = g_hd[0][l][(size_t)(row0 + row)*Hq + gc0 + col];
        }

    unsigned seq = 0;
    for (int t = 0; t < LTq; t++) {
        int p = t & 1;
        dec_gru_stage(dsm, 0, p, hdreg[0], g_dwih_h, g_dwih_l, g_dwhh_h, g_dwhh_l,
                      dec_bih, dec_bhh);
        dec_gridbar(++seq);
        dec_gru_stage(dsm, 1, p, hdreg[1],
                      g_dwih_h + (size_t)H3q*Hq, g_dwih_l + (size_t)H3q*Hq,
                      g_dwhh_h + (size_t)H3q*Hq, g_dwhh_l + (size_t)H3q*Hq,
                      dec_bih + H3q, dec_bhh + H3q);
        dec_gridbar(++seq);
        dec_attn_stage(dsm, t, p, attn_out);
        dec_gridbar(++seq);
        dec_attfc_stage(dsm, p, Watt, batt);
        dec_gridbar(++seq);
        dec_out_stage(dsm, t, Wout, bout, vecout);
        dec_gridbar(++seq);
    }
}

// ---------------- final hidden copy ----------------
__global__ void k_hfinal(float* __restrict__ out) {
    int idx = blockIdx.x * blockDim.x + threadIdx.x;
    if (idx < NLq*Bq*Hq) out[idx] = (&g_hd[0][0][0])[idx];
}

// ---------------- launch ----------------
extern "C" void kernel_launch(void* const* d_in, const int* in_sizes, int n_in,
                              void* d_out, int out_size) {
    const float* x        = (const float*)d_in[0];
    const float* emb      = (const float*)d_in[2];
    const float* W_enc    = (const float*)d_in[3];
    const float* b_enc    = (const float*)d_in[4];
    const float* enc0_Wih = (const float*)d_in[5];
    const float* enc0_Whh = (const float*)d_in[6];
    const float* enc0_bih = (const float*)d_in[7];
    const float* enc0_bhh = (const float*)d_in[8];
    const float* enc1_Wih = (const float*)d_in[9];
    const float* enc1_Whh = (const float*)d_in[10];
    const float* enc1_bih = (const float*)d_in[11];
    const float* enc1_bhh = (const float*)d_in[12];
    const float* W_bi     = (const float*)d_in[13];
    const float* b_bi     = (const float*)d_in[14];
    const float* dec_Wih  = (const float*)d_in[15];
    const float* dec_Whh  = (const float*)d_in[16];
    const float* dec_bih  = (const float*)d_in[17];
    const float* dec_bhh  = (const float*)d_in[18];
    const float* W_att    = (const float*)d_in[19];
    const float* b_att    = (const float*)d_in[20];
    const float* W_out    = (const float*)d_in[21];
    const float* b_out    = (const float*)d_in[22];

    float* out_vec  = (float*)d_out;
    float* out_h    = out_vec + (size_t)Bq*LTq*Vq;
    float* out_attn = out_h + (size_t)NLq*Bq*Hq;

    cudaFuncSetAttribute(k_enc_mma, cudaFuncAttributeMaxDynamicSharedMemorySize, ENC_SMEM);
    cudaFuncSetAttribute(k_dec_pers, cudaFuncAttributeMaxDynamicSharedMemorySize, DEC_SMEM);
    cudaFuncSetAttribute(k_gemm_mma, cudaFuncAttributeMaxDynamicSharedMemorySize, GEMM_SMEM);

    __nv_bfloat16 *xr_h, *xr_l, *y0_h, *y0_l, *y1_h, *y1_l, *w0_h, *w0_l, *w1_h, *w1_l, *wb_h, *wb_l;
    __nv_bfloat16 *dwih_h, *dwih_l, *dwhh_h, *dwhh_l, *emb_h, *emb_l;
    cudaGetSymbolAddress((void**)&xr_h, g_xr_h); cudaGetSymbolAddress((void**)&xr_l, g_xr_l);
    cudaGetSymbolAddress((void**)&y0_h, g_y0_h); cudaGetSymbolAddress((void**)&y0_l, g_y0_l);
    cudaGetSymbolAddress((void**)&y1_h, g_y1_h); cudaGetSymbolAddress((void**)&y1_l, g_y1_l);
    cudaGetSymbolAddress((void**)&w0_h, g_w0_h); cudaGetSymbolAddress((void**)&w0_l, g_w0_l);
    cudaGetSymbolAddress((void**)&w1_h, g_w1_h); cudaGetSymbolAddress((void**)&w1_l, g_w1_l);
    cudaGetSymbolAddress((void**)&wb_h, g_wb_h); cudaGetSymbolAddress((void**)&wb_l, g_wb_l);
    cudaGetSymbolAddress((void**)&dwih_h, g_dwih_h); cudaGetSymbolAddress((void**)&dwih_l, g_dwih_l);
    cudaGetSymbolAddress((void**)&dwhh_h, g_dwhh_h); cudaGetSymbolAddress((void**)&dwhh_l, g_dwhh_l);
    cudaGetSymbolAddress((void**)&emb_h, g_emb_h); cudaGetSymbolAddress((void**)&emb_l, g_emb_l);
    float* gi_f; cudaGetSymbolAddress((void**)&gi_f, g_gi);
    float* v_f;  cudaGetSymbolAddress((void**)&v_f,  g_v);

    k_proj<<<(Mq*Hq + 255)/256, 256>>>(x, W_enc, b_enc);                            // 0
    k_cvt<<<(2*H3q*Hq/4 + 255)/256, 256>>>(enc0_Wih, w0_h, w0_l, 2*H3q*Hq/4);       // 1
    k_gemm_mma<<<dim3(H3q/128, Mq/128, 2), 256, GEMM_SMEM>>>(                        // 2
        xr_h, xr_l, w0_h, w0_l, enc0_bih, gi_f,
        Hq, H3q, (size_t)H3q*Hq, H3q, (size_t)Mq*H3q);
    k_enc_mma<<<128, 256, ENC_SMEM>>>(enc0_Whh, enc0_bhh, 0);                        // 3 <- profiled
    k_cvt<<<(2*H3q*2*Hq/4 + 255)/256, 256>>>(enc1_Wih, w1_h, w1_l, 2*H3q*2*Hq/4);
    k_cvt<<<(Hq*2*Hq/4 + 255)/256, 256>>>(W_bi, wb_h, wb_l, Hq*2*Hq/4);
    k_cvt<<<(NLq*H3q*Hq/4 + 255)/256, 256>>>(dec_Wih, dwih_h, dwih_l, NLq*H3q*Hq/4);
    k_cvt<<<(NLq*H3q*Hq/4 + 255)/256, 256>>>(dec_Whh, dwhh_h, dwhh_l, NLq*H3q*Hq/4);
    k_cvt<<<(Vq*Hq/4 + 255)/256, 256>>>(emb, emb_h, emb_l, Vq*Hq/4);

    // layer 1
    k_gemm_mma<<<dim3(H3q/128, Mq/128, 2), 256, GEMM_SMEM>>>(
        y0_h, y0_l, w1_h, w1_l, enc1_bih, gi_f,
        2*Hq, H3q, (size_t)H3q*2*Hq, H3q, (size_t)Mq*H3q);
    k_enc_mma<<<128, 256, ENC_SMEM>>>(enc1_Whh, enc1_bhh, 1);

    // bi_fc + norms
    k_gemm_mma<<<dim3(Hq/128, Mq/128, 1), 256, GEMM_SMEM>>>(
        y1_h, y1_l, wb_h, wb_l, b_bi, v_f,
        2*Hq, Hq, 0, 0, 0);
    k_vn<<<Mq, 128>>>();

    // persistent decoder
    k_initdec<<<(Bq*Hq + 255)/256, 256>>>();
    k_dec_pers<<<128, 256, DEC_SMEM>>>(dec_bih, dec_bhh, W_att, b_att,
                                       W_out, b_out, out_vec, out_attn);
    k_hfinal<<<(NLq*Bq*Hq + 255)/256, 256>>>(out_h);
    (void)in_sizes; (void)n_in; (void)out_size;
}

// round 17
// speedup vs baseline: 1.0685x; 1.0222x over previous
#include <cuda_runtime.h>
#include <cuda_bf16.h>
#include <math.h>
#include <stdint.h>

#define Bq 128
#define Hq 512
#define LCq 256
#define LTq 64
#define Vq 27
#define NLq 2
#define H3q (3*Hq)
#define KT 32
#define Mq (LCq*Bq)

// ---------------- scratch ----------------
__device__ float g_gi[(size_t)2*Mq*H3q];
__device__ float g_y0[(size_t)Mq*2*Hq];
__device__ float g_y1[(size_t)Mq*2*Hq];
__device__ float g_v [(size_t)Mq*Hq];
__device__ float g_vn[Mq];
__device__ float g_hd[2][NLq][Bq*Hq];
__device__ float g_a [Bq*Hq];
__device__ float g_hid[Bq*Hq];
__device__ int   g_vecin[Bq];
__device__ unsigned g_barc[2][4*32];
__device__ unsigned g_dbar[4*32];

// bf16 hi/lo decompositions
__device__ __nv_bfloat16 g_xr_h[(size_t)Mq*Hq],   g_xr_l[(size_t)Mq*Hq];
__device__ __nv_bfloat16 g_y0_h[(size_t)Mq*2*Hq], g_y0_l[(size_t)Mq*2*Hq];
__device__ __nv_bfloat16 g_y1_h[(size_t)Mq*2*Hq], g_y1_l[(size_t)Mq*2*Hq];
__device__ __nv_bfloat16 g_w0_h[2*H3q*Hq],   g_w0_l[2*H3q*Hq];
__device__ __nv_bfloat16 g_w1_h[2*H3q*2*Hq], g_w1_l[2*H3q*2*Hq];
__device__ __nv_bfloat16 g_wb_h[Hq*2*Hq],    g_wb_l[Hq*2*Hq];
// decoder bf16
__device__ __nv_bfloat16 g_dwih_h[NLq*H3q*Hq], g_dwih_l[NLq*H3q*Hq];
__device__ __nv_bfloat16 g_dwhh_h[NLq*H3q*Hq], g_dwhh_l[NLq*H3q*Hq];
__device__ __nv_bfloat16 g_emb_h[Vq*Hq], g_emb_l[Vq*Hq];
__device__ __nv_bfloat16 g_hdh[2][NLq][Bq*Hq], g_hdl[2][NLq][Bq*Hq];

// ---------------- warp-mma primitives ----------------
__device__ __forceinline__ uint32_t smem_u32(const void* p) {
    uint32_t a;
    asm("{ .reg .u64 t; cvta.to.shared.u64 t, %1; cvt.u32.u64 %0, t; }" : "=r"(a) : "l"(p));
    return a;
}
__device__ __forceinline__ void ldsm4(uint32_t& r0, uint32_t& r1, uint32_t& r2, uint32_t& r3,
                                      uint32_t a) {
    asm volatile("ldmatrix.sync.aligned.m8n8.x4.shared.b16 {%0,%1,%2,%3}, [%4];"
        : "=r"(r0), "=r"(r1), "=r"(r2), "=r"(r3) : "r"(a));
}
__device__ __forceinline__ void ldsm2(uint32_t& r0, uint32_t& r1, uint32_t a) {
    asm volatile("ldmatrix.sync.aligned.m8n8.x2.shared.b16 {%0,%1}, [%2];"
        : "=r"(r0), "=r"(r1) : "r"(a));
}
__device__ __forceinline__ void mma_bf16(float* c, const uint32_t* a, const uint32_t* b) {
    asm volatile("mma.sync.aligned.m16n8k16.row.col.f32.bf16.bf16.f32 "
        "{%0,%1,%2,%3}, {%4,%5,%6,%7}, {%8,%9}, {%0,%1,%2,%3};"
        : "+f"(c[0]), "+f"(c[1]), "+f"(c[2]), "+f"(c[3])
        : "r"(a[0]), "r"(a[1]), "r"(a[2]), "r"(a[3]), "r"(b[0]), "r"(b[1]));
}
__device__ __forceinline__ void cpa16(uint32_t s, const void* g) {
    asm volatile("cp.async.ca.shared.global [%0], [%1], 16;" :: "r"(s), "l"(g));
}
#define CP_COMMIT()  asm volatile("cp.async.commit_group;" ::: "memory")
#define CP_WAIT_1()  asm volatile("cp.async.wait_group 1;" ::: "memory")
#define CP_WAIT_0()  asm volatile("cp.async.wait_group 0;" ::: "memory")

// release/acquire barrier primitives (no MEMBAR drain on the issuing warp)
__device__ __forceinline__ void red_release(unsigned* p) {
    asm volatile("red.release.gpu.add.u32 [%0], 1;" :: "l"(p) : "memory");
}
__device__ __forceinline__ unsigned ld_acquire(const unsigned* p) {
    unsigned v;
    asm volatile("ld.acquire.gpu.u32 %0, [%1];" : "=r"(v) : "l"(p) : "memory");
    return v;
}

// ---------------- fp32 -> bf16 hi/lo split ----------------
__global__ void k_cvt(const float* __restrict__ s, __nv_bfloat16* __restrict__ hi,
                      __nv_bfloat16* __restrict__ lo, int n4) {
    int i = blockIdx.x * blockDim.x + threadIdx.x;
    if (i >= n4) return;
    float4 v = *(const float4*)(s + (size_t)i*4);
    __nv_bfloat16 h0 = __float2bfloat16(v.x), h1 = __float2bfloat16(v.y);
    __nv_bfloat16 h2 = __float2bfloat16(v.z), h3 = __float2bfloat16(v.w);
    __nv_bfloat162 hA, hB, lA, lB;
    hA.x = h0; hA.y = h1; hB.x = h2; hB.y = h3;
    lA.x = __float2bfloat16(v.x - __bfloat162float(h0));
    lA.y = __float2bfloat16(v.y - __bfloat162float(h1));
    lB.x = __float2bfloat16(v.z - __bfloat162float(h2));
    lB.y = __float2bfloat16(v.w - __bfloat162float(h3));
    *(__nv_bfloat162*)(hi + (size_t)i*4)     = hA;
    *(__nv_bfloat162*)(hi + (size_t)i*4 + 2) = hB;
    *(__nv_bfloat162*)(lo + (size_t)i*4)     = lA;
    *(__nv_bfloat162*)(lo + (size_t)i*4 + 2) = lB;
}

// ---------------- encoder input projection (fused hi/lo + barrier reset) -------
__global__ void k_proj(const float* __restrict__ x, const float* __restrict__ W_enc,
                       const float* __restrict__ b_enc) {
    int idx = blockIdx.x * blockDim.x + threadIdx.x;
    if (blockIdx.x == 0 && threadIdx.x == 0) {
        for (int i = 0; i < 2; i++)
            for (int j = 0; j < 4; j++) g_barc[i][j*32] = 0;
        for (int j = 0; j < 4; j++) g_dbar[j*32] = 0;
    }
    if (idx >= Mq*Hq) return;
    int h = idx % Hq; int bl = idx / Hq; int b = bl % Bq; int l = bl / Bq;
    float v = x[(size_t)b*2*LCq + l] * W_enc[h*2]
            + x[(size_t)b*2*LCq + LCq + l] * W_enc[h*2+1] + b_enc[h];
    __nv_bfloat16 hv = __float2bfloat16(v);
    g_xr_h[idx] = hv;
    g_xr_l[idx] = __float2bfloat16(v - __bfloat162float(hv));
}

// ---------------- tensor-core GEMM: CTA 128x128, warp 32x64, cp.async ---------
#define AROW 40
#define GT (128*AROW)
#define GEMM_SMEM (8*GT*2)
__global__ void __launch_bounds__(256) k_gemm_mma(
        const __nv_bfloat16* __restrict__ Ah, const __nv_bfloat16* __restrict__ Al,
        const __nv_bfloat16* __restrict__ Wh, const __nv_bfloat16* __restrict__ Wl,
        const float* __restrict__ bias, float* __restrict__ C,
        int K, int Nld, size_t wStrideZ, int bStrideZ, size_t cStrideZ) {
    extern __shared__ __nv_bfloat16 gsm[];
    __nv_bfloat16* sAh = gsm;
    __nv_bfloat16* sAl = gsm + 2*GT;
    __nv_bfloat16* sWh = gsm + 4*GT;
    __nv_bfloat16* sWl = gsm + 6*GT;

    int tid = threadIdx.x, wid = tid >> 5, lane = tid & 31;
    int z = blockIdx.z;
    const __nv_bfloat16* Whz = Wh + (size_t)z*wStrideZ;
    const __nv_bfloat16* Wlz = Wl + (size_t)z*wStrideZ;
    const float* bias_z = bias + (size_t)z*bStrideZ;
    float* C_z = C + (size_t)z*cStrideZ;
    int col0 = blockIdx.x * 128, row0 = blockIdx.y * 128;
    int wm = (wid & 3) * 32, wn = (wid >> 2) * 64;

    float acc[2][8][4];
    #pragma unroll
    for (int i = 0; i < 2; i++)
        #pragma unroll
        for (int j = 0; j < 8; j++)
            #pragma unroll
            for (int k = 0; k < 4; k++) acc[i][j][k] = 0.f;

    uint32_t aBase = smem_u32(sAh), alBase = smem_u32(sAl);
    uint32_t wBase = smem_u32(sWh), wlBase = smem_u32(sWl);
    int aRow = wm + (lane & 15);
    int aCol = (lane >> 4) * 8;
    int g = lane >> 3;
    int bRow = wn + (lane & 7) + ((g >> 1) & 1) * 8;
    int bCol = (g & 1) * 8;

    int r0 = tid >> 2, c0 = tid & 3;
    int r1 = (tid + 256) >> 2, c1 = (tid + 256) & 3;
    uint32_t sOff0 = (uint32_t)((r0*AROW + c0*8) * 2);
    uint32_t sOff1 = (uint32_t)((r1*AROW + c1*8) * 2);
    size_t goA0 = (size_t)(row0 + r0)*K + c0*8;
    size_t goA1 = (size_t)(row0 + r1)*K + c1*8;
    size_t goW0 = (size_t)(col0 + r0)*K + c0*8;
    size_t goW1 = (size_t)(col0 + r1)*K + c1*8;

    int nk = K >> 5;
    {
        cpa16(aBase  + sOff0, Ah + goA0);  cpa16(aBase  + sOff1, Ah + goA1);
        cpa16(alBase + sOff0, Al + goA0);  cpa16(alBase + sOff1, Al + goA1);
        cpa16(wBase  + sOff0, Whz + goW0); cpa16(wBase  + sOff1, Whz + goW1);
        cpa16(wlBase + sOff0, Wlz + goW0); cpa16(wlBase + sOff1, Wlz + goW1);
        CP_COMMIT();
    }
    int buf = 0;
    for (int kc = 0; kc < nk; kc++) {
        if (kc + 1 < nk) {
            int kn = (kc + 1) << 5;
            uint32_t bo = (uint32_t)((buf ^ 1) * GT * 2);
            cpa16(aBase  + bo + sOff0, Ah + goA0 + kn);  cpa16(aBase  + bo + sOff1, Ah + goA1 + kn);
            cpa16(alBase + bo + sOff0, Al + goA0 + kn);  cpa16(alBase + bo + sOff1, Al + goA1 + kn);
            cpa16(wBase  + bo + sOff0, Whz + goW0 + kn); cpa16(wBase  + bo + sOff1, Whz + goW1 + kn);
            cpa16(wlBase + bo + sOff0, Wlz + goW0 + kn); cpa16(wlBase + bo + sOff1, Wlz + goW1 + kn);
            CP_COMMIT();
            CP_WAIT_1();
        } else {
            CP_WAIT_0();
        }
        __syncthreads();

        uint32_t abH = aBase  + (uint32_t)(buf*GT*2);
        uint32_t abL = alBase + (uint32_t)(buf*GT*2);
        uint32_t wbH = wBase  + (uint32_t)(buf*GT*2);
        uint32_t wbL = wlBase + (uint32_t)(buf*GT*2);

        #pragma unroll
        for (int ks = 0; ks < 2; ks++) {
            uint32_t ah[2][4], al[2][4];
            #pragma unroll
            for (int mi = 0; mi < 2; mi++) {
                uint32_t off = (uint32_t)(((aRow + mi*16)*AROW + ks*16 + aCol) * 2);
                ldsm4(ah[mi][0], ah[mi][1], ah[mi][2], ah[mi][3], abH + off);
                ldsm4(al[mi][0], al[mi][1], al[mi][2], al[mi][3], abL + off);
            }
            #pragma unroll
            for (int ng = 0; ng < 4; ng++) {
                uint32_t bh[4], bl[4];
                uint32_t off = (uint32_t)(((bRow + ng*16)*AROW + ks*16 + bCol) * 2);
                ldsm4(bh[0], bh[1], bh[2], bh[3], wbH + off);
                ldsm4(bl[0], bl[1], bl[2], bl[3], wbL + off);
                #pragma unroll
                for (int mi = 0; mi < 2; mi++)
                    #pragma unroll
                    for (int half = 0; half < 2; half++) {
                        float* c = acc[mi][ng*2 + half];
                        mma_bf16(c, ah[mi], &bh[half*2]);
                        mma_bf16(c, ah[mi], &bl[half*2]);
                        mma_bf16(c, al[mi], &bh[half*2]);
                    }
            }
        }
        __syncthreads();
        buf ^= 1;
    }

    #pragma unroll
    for (int mi = 0; mi < 2; mi++) {
        int r_ = row0 + wm + mi*16 + (lane >> 2);
        #pragma unroll
        for (int ni = 0; ni < 8; ni++) {
            int c_ = col0 + wn + ni*8 + (lane & 3)*2;
            float b0 = bias_z[c_], b1 = bias_z[c_ + 1];
            float2 o0 = { acc[mi][ni][0] + b0, acc[mi][ni][1] + b1 };
            float2 o1 = { acc[mi][ni][2] + b0, acc[mi][ni][3] + b1 };
            *(float2*)(C_z + (size_t)r_*Nld + c_)       = o0;
            *(float2*)(C_z + (size_t)(r_ + 8)*Nld + c_) = o1;
        }
    }
}

// ---------------- persistent MMA encoder GRU layer ----------------
#define WP 520
#define AP 136
#define ENC_SMEM ((96*WP + 4*64*AP) * 2)
__global__ void __launch_bounds__(256, 1) k_enc_mma(
        const float* __restrict__ Whh2, const float* __restrict__ bhh2, int layer) {
    extern __shared__ __nv_bfloat16 smb[];
    __nv_bfloat16* sWh = smb;
    __nv_bfloat16* sWl = smb + 48*WP;
    __nv_bfloat16* sAh = smb + 96*WP;
    __nv_bfloat16* sAl = smb + 96*WP + 2*64*AP;

    float* Y = layer ? g_y1 : g_y0;
    __nv_bfloat16* Yh = layer ? g_y1_h : g_y0_h;
    __nv_bfloat16* Yl = layer ? g_y1_l : g_y0_l;

    int bid = blockIdx.x;
    int dirv = bid >> 6;
    int rem = bid & 63;
    int cg = rem & 31;
    int bg = rem >> 5;
    int gc0 = cg * 16;
    int row0 = bg * 64;
    unsigned grp = ((unsigned)dirv << 1) | (unsigned)bg;

    int tid = threadIdx.x, wid = tid >> 5, lane = tid & 31;
    int wm = (wid & 3) * 16;
    int ws = wid >> 2;

    const float* Whh = Whh2 + (size_t)dirv*H3q*Hq;
    const float* bhh = bhh2 + dirv*H3q;

    for (int u = tid; u < 48*128; u += 256) {
        int rrow = u >> 7, kq = u & 127;
        int g = rrow >> 4, c = rrow & 15;
        float4 w = __ldg((const float4*)(Whh + (size_t)(g*Hq + gc0 + c)*Hq) + kq);
        __nv_bfloat16 h0 = __float2bfloat16(w.x), h1 = __float2bfloat16(w.y);
        __nv_bfloat16 h2 = __float2bfloat16(w.z), h3 = __float2bfloat16(w.w);
        __nv_bfloat162 hh0; hh0.x = h0; hh0.y = h1;
        __nv_bfloat162 hh1; hh1.x = h2; hh1.y = h3;
        __nv_bfloat162 ll0, ll1;
        ll0.x = __float2bfloat16(w.x - __bfloat162float(h0));
        ll0.y = __float2bfloat16(w.y - __bfloat162float(h1));
        ll1.x = __float2bfloat16(w.z - __bfloat162float(h2));
        ll1.y = __float2bfloat16(w.w - __bfloat162float(h3));
        *(__nv_bfloat162*)(sWh + rrow*WP + kq*4)     = hh0;
        *(__nv_bfloat162*)(sWh + rrow*WP + kq*4 + 2) = hh1;
        *(__nv_bfloat162*)(sWl + rrow*WP + kq*4)     = ll0;
        *(__nv_bfloat162*)(sWl + rrow*WP + kq*4 + 2) = ll1;
    }
    int cA = gc0 + ws*8 + 2*(lane & 3);
    float br0 = __ldg(bhh + cA),        br1 = __ldg(bhh + cA + 1);
    float bz0 = __ldg(bhh + 512 + cA),  bz1 = __ldg(bhh + 512 + cA + 1);
    float bn0 = __ldg(bhh + 1024 + cA), bn1 = __ldg(bhh + 1024 + cA + 1);
    __syncthreads();

    uint32_t aBaseH = smem_u32(sAh), aBaseL = smem_u32(sAl);
    uint32_t wBaseH = smem_u32(sWh), wBaseL = smem_u32(sWl);
    uint32_t aOff = (uint32_t)(((wm + (lane & 15))*AP + (lane >> 4)*8) * 2);
    int bRow = ws*8 + (lane & 7);
    uint32_t bColOff = (uint32_t)((((lane >> 3) & 1) * 8) * 2);

    int sr[4], sc[4];
    #pragma unroll
    for (int i = 0; i < 4; i++) {
        int slot = tid + i*256;
        sr[i] = slot >> 4; sc[i] = slot & 15;
    }

    float2 hpreg[2];
    hpreg[0] = make_float2(0.f, 0.f);
    hpreg[1] = make_float2(0.f, 0.f);

    for (int s = 0; s < LCq; s++) {
        int t = dirv ? (LCq-1-s) : s;
        int tprev = dirv ? (t+1) : (t-1);

        const float* gi_t = g_gi + ((size_t)dirv*LCq + t)*Bq*H3q;
        float2 gr[2], gz[2], gn[2];
        #pragma unroll
        for (int rr = 0; rr < 2; rr++) {
            int b = row0 + wm + (lane >> 2) + rr*8;
            const float* gib = gi_t + (size_t)b*H3q;
            gr[rr] = __ldg((const float2*)(gib + cA));
            gz[rr] = __ldg((const float2*)(gib + 512 + cA));
            gn[rr] = __ldg((const float2*)(gib + 1024 + cA));
        }

        float acc[3][4];
        #pragma unroll
        for (int g = 0; g < 3; g++) {
            acc[g][0] = acc[g][1] = acc[g][2] = acc[g][3] = 0.f;
        }

        if (s > 0) {
            const __nv_bfloat16* Ahp = Yh + ((size_t)tprev*Bq)*2*Hq + (size_t)dirv*Hq;
            const __nv_bfloat16* Alp = Yl + ((size_t)tprev*Bq)*2*Hq + (size_t)dirv*Hq;
            uint4 ph[4], pl[4];
            #pragma unroll
            for (int i = 0; i < 4; i++) {
                ph[i] = __ldcg((const uint4*)(Ahp + (size_t)(row0 + sr[i])*2*Hq + sc[i]*8));
                pl[i] = __ldcg((const uint4*)(Alp + (size_t)(row0 + sr[i])*2*Hq + sc[i]*8));
            }
            int buf = 0;
            for (int kc = 0; kc < 4; kc++) {
                __nv_bfloat16* dAh = sAh + buf*64*AP;
                __nv_bfloat16* dAl = sAl + buf*64*AP;
                #pragma unroll
                for (int i = 0; i < 4; i++) {
                    *(uint4*)(dAh + sr[i]*AP + sc[i]*8) = ph[i];
                    *(uint4*)(dAl + sr[i]*AP + sc[i]*8) = pl[i];
                }
                __syncthreads();
                if (kc < 3) {
                    int k1 = (kc + 1)*128;
                    #pragma unroll
                    for (int i = 0; i < 4; i++) {
                        ph[i] = __ldcg((const uint4*)(Ahp + (size_t)(row0 + sr[i])*2*Hq + k1 + sc[i]*8));
                        pl[i] = __ldcg((const uint4*)(Alp + (size_t)(row0 + sr[i])*2*Hq + k1 + sc[i]*8));
                    }
                }
                int k0 = kc*128;
                uint32_t abH = aBaseH + (uint32_t)(buf*64*AP*2);
                uint32_t abL = aBaseL + (uint32_t)(buf*64*AP*2);
                #pragma unroll
                for (int ks = 0; ks < 8; ks++) {
                    uint32_t ah[4], al[4];
                    uint32_t ao = aOff + (uint32_t)(ks*32);
                    ldsm4(ah[0], ah[1], ah[2], ah[3], abH + ao);
                    ldsm4(al[0], al[1], al[2], al[3], abL + ao);
                    #pragma unroll
                    for (int g = 0; g < 3; g++) {
                        uint32_t bh[2], bl[2];
                        uint32_t wo = (uint32_t)((((g*16 + bRow)*WP) + k0 + ks*16)*2) + bColOff;
                        ldsm2(bh[0], bh[1], wBaseH + wo);
                        ldsm2(bl[0], bl[1], wBaseL + wo);
                        mma_bf16(acc[g], ah, bh);
                        mma_bf16(acc[g], ah, bl);
                        mma_bf16(acc[g], al, bh);
                    }
                }
                __syncthreads();
                buf ^= 1;
            }
        }

        #pragma unroll
        for (int rr = 0; rr < 2; rr++) {
            int b = row0 + wm + (lane >> 2) + rr*8;
            float r0v = 1.f/(1.f + expf(-(gr[rr].x + acc[0][rr*2]   + br0)));
            float r1v = 1.f/(1.f + expf(-(gr[rr].y + acc[0][rr*2+1] + br1)));
            float z0v = 1.f/(1.f + expf(-(gz[rr].x + acc[1][rr*2]   + bz0)));
            float z1v = 1.f/(1.f + expf(-(gz[rr].y + acc[1][rr*2+1] + bz1)));
            float n0v = tanhf(gn[rr].x + r0v*(acc[2][rr*2]   + bn0));
            float n1v = tanhf(gn[rr].y + r1v*(acc[2][rr*2+1] + bn1));
            float h0v = (1.f - z0v)*n0v + z0v*hpreg[rr].x;
            float h1v = (1.f - z1v)*n1v + z1v*hpreg[rr].y;
            hpreg[rr] = make_float2(h0v, h1v);
            size_t o = ((size_t)t*Bq + b)*2*Hq + (size_t)dirv*Hq + cA;
            if (layer == 0 && s == LCq-1)
                *(float2*)(Y + o) = hpreg[rr];
            __nv_bfloat16 bh0 = __float2bfloat16(h0v), bh1 = __float2bfloat16(h1v);
            __nv_bfloat162 hv; hv.x = bh0; hv.y = bh1;
            __nv_bfloat162 lv;
            lv.x = __float2bfloat16(h0v - __bfloat162float(bh0));
            lv.y = __float2bfloat16(h1v - __bfloat162float(bh1));
            *(__nv_bfloat162*)(Yh + o) = hv;
            *(__nv_bfloat162*)(Yl + o) = lv;
        }

        __syncthreads();
        if (tid == 0) {
            unsigned* ctr = &g_barc[layer][grp*32];
            red_release(ctr);
            unsigned target = 32u * (unsigned)(s + 1);
            while (ld_acquire(ctr) < target) { }
        }
        __syncthreads();
    }
}

// ---------------- v row norms ----------------
__global__ void k_vn() {
    int row = blockIdx.x;
    int tid = threadIdx.x;
    const float* vr = g_v + (size_t)row*Hq;
    float s = 0.f;
    for (int k = tid; k < Hq; k += 128) { float x = vr[k]; s = fmaf(x, x, s); }
    __shared__ float red[128];
    red[tid] = s; __syncthreads();
    for (int o = 64; o > 0; o >>= 1) { if (tid < o) red[tid] += red[tid + o]; __syncthreads(); }
    if (tid == 0) g_vn[row] = fmaxf(sqrtf(red[0]), 1e-8f);
}

// ---------------- decoder init (fp32 + hi/lo) ----------------
__global__ void k_initdec() {
    int idx = blockIdx.x * blockDim.x + threadIdx.x;
    if (idx < Bq) g_vecin[idx] = 0;
    if (idx < Bq*Hq) {
        int b = idx / Hq, h = idx % Hq;
        float h0 = g_y0[((size_t)(LCq-1)*Bq + b)*2*Hq + h];
        float h1 = g_y0[((size_t)b)*2*Hq + Hq + h];
        g_hd[0][0][idx] = h0;
        g_hd[0][1][idx] = h1;
        __nv_bfloat16 a = __float2bfloat16(h0);
        __nv_bfloat16 c = __float2bfloat16(h1);
        g_hdh[0][0][idx] = a;
        g_hdl[0][0][idx] = __float2bfloat16(h0 - __bfloat162float(a));
        g_hdh[0][1][idx] = c;
        g_hdl[0][1][idx] = __float2bfloat16(h1 - __bfloat162float(c));
    }
}

// ================= persistent decoder =================
#define DEC_SMEM 55296

// group-local release/acquire barrier
__device__ __forceinline__ void dec_gridbar(unsigned seq) {
    __syncthreads();
    if (threadIdx.x == 0) {
        unsigned grp = blockIdx.x >> 5;
        unsigned* ctr = &g_dbar[grp*32];
        red_release(ctr);
        unsigned t = 32u * seq;
        while (ld_acquire(ctr) < t) { }
    }
    __syncthreads();
}

__device__ void dec_gru_stage(char* sm, int l, int p, float* hreg,
        const __nv_bfloat16* __restrict__ Wih_h, const __nv_bfloat16* __restrict__ Wih_l,
        const __nv_bfloat16* __restrict__ Whh_h, const __nv_bfloat16* __restrict__ Whh_l,
        const float* __restrict__ bih, const float* __restrict__ bhh) {
    __nv_bfloat16* sWh = (__nv_bfloat16*)sm;
    __nv_bfloat16* sWl = sWh + 96*72;
    __nv_bfloat16* sXh = sWl + 96*72;
    __nv_bfloat16* sXl = sXh + 32*72;
    __nv_bfloat16* sHh = sXl + 32*72;
    __nv_bfloat16* sHl = sHh + 32*72;
    float* sAcc = (float*)(sHl + 32*72);
    int* vs = (int*)(sAcc + 4*32*17);

    int tid = threadIdx.x, lane = tid & 31, wid = tid >> 5;
    int cg = blockIdx.x & 31, bg = blockIdx.x >> 5;
    int gc0 = cg * 16, row0 = bg * 32;
    int wm16 = (wid & 1) * 16;
    int wq = wid >> 1;

    if (l == 0 && tid < 32) vs[tid] = __ldcg(&g_vecin[row0 + tid]);

    const __nv_bfloat16* Hh = g_hdh[p][l];
    const __nv_bfloat16* Hl = g_hdl[p][l];
    const __nv_bfloat16* Xh_g = (l == 0) ? g_emb_h : g_hdh[1-p][0];
    const __nv_bfloat16* Xl_g = (l == 0) ? g_emb_l : g_hdl[1-p][0];

    float acc[2][4] = {{0,0,0,0},{0,0,0,0}};

    uint32_t aXh = smem_u32(sXh), aXl = smem_u32(sXl);
    uint32_t aHh = smem_u32(sHh), aHl = smem_u32(sHl);
    uint32_t wBh = smem_u32(sWh), wBl = smem_u32(sWl);
    uint32_t aOffBase = (uint32_t)(((wm16 + (lane & 15))*72 + (lane >> 4)*8) * 2);
    int bRowIn = (lane & 7) + ((lane >> 4) & 1)*8;
    uint32_t bColOff = (uint32_t)((((lane >> 3) & 1) * 8) * 2);

    __syncthreads();

    for (int kc = 0; kc < 8; kc++) {
        int k0 = kc * 64;
        #pragma unroll
        for (int i = 0; i < 3; i++) {
            int u = tid + i*256;
            int rr = u >> 3, ku = u & 7;
            int grow = rr < 48 ? rr : rr - 48;
            int g = grow >> 4, c = grow & 15;
            size_t src = (size_t)(g*Hq + gc0 + c)*Hq + k0 + ku*8;
            const __nv_bfloat16* MH = rr < 48 ? Wih_h : Whh_h;
            const __nv_bfloat16* ML = rr < 48 ? Wih_l : Whh_l;
            *(uint4*)(sWh + rr*72 + ku*8) = *(const uint4*)(MH + src);
            *(uint4*)(sWl + rr*72 + ku*8) = *(const uint4*)(ML + src);
        }
        {
            int rr = tid >> 3, ku = tid & 7;
            size_t xoff;
            if (l == 0) xoff = (size_t)vs[rr]*Hq + k0 + ku*8;
            else        xoff = (size_t)(row0 + rr)*Hq + k0 + ku*8;
            if (l == 0) {
                *(uint4*)(sXh + rr*72 + ku*8) = *(const uint4*)(Xh_g + xoff);
                *(uint4*)(sXl + rr*72 + ku*8) = *(const uint4*)(Xl_g + xoff);
            } else {
                *(uint4*)(sXh + rr*72 + ku*8) = __ldcg((const uint4*)(Xh_g + xoff));
                *(uint4*)(sXl + rr*72 + ku*8) = __ldcg((const uint4*)(Xl_g + xoff));
            }
            size_t hoff = (size_t)(row0 + rr)*Hq + k0 + ku*8;
            *(uint4*)(sHh + rr*72 + ku*8) = __ldcg((const uint4*)(Hh + hoff));
            *(uint4*)(sHl + rr*72 + ku*8) = __ldcg((const uint4*)(Hl + hoff));
        }
        __syncthreads();

        #pragma unroll
        for (int ks = 0; ks < 4; ks++) {
            uint32_t ao = aOffBase + (uint32_t)(ks*32);
            uint32_t coff = bColOff + (uint32_t)(ks*32);
            if (wq < 2) {
                uint32_t axh[4], axl[4], ahh[4], ahl[4];
                ldsm4(axh[0], axh[1], axh[2], axh[3], aXh + ao);
                ldsm4(axl[0], axl[1], axl[2], axl[3], aXl + ao);
                ldsm4(ahh[0], ahh[1], ahh[2], ahh[3], aHh + ao);
                ldsm4(ahl[0], ahl[1], ahl[2], ahl[3], aHl + ao);
                int gih = wq*16, ghh = 48 + wq*16;
                uint32_t bih_h[4], bih_l[4], bhh_h[4], bhh_l[4];
                uint32_t oi = (uint32_t)(((gih + bRowIn)*72)*2) + coff;
                uint32_t oh = (uint32_t)(((ghh + bRowIn)*72)*2) + coff;
                ldsm4(bih_h[0], bih_h[1], bih_h[2], bih_h[3], wBh + oi);
                ldsm4(bih_l[0], bih_l[1], bih_l[2], bih_l[3], wBl + oi);
                ldsm4(bhh_h[0], bhh_h[1], bhh_h[2], bhh_h[3], wBh + oh);
                ldsm4(bhh_l[0], bhh_l[1], bhh_l[2], bhh_l[3], wBl + oh);
                #pragma unroll
                for (int ni = 0; ni < 2; ni++) {
                    mma_bf16(acc[ni], axh, &bih_h[ni*2]);
                    mma_bf16(acc[ni], axh, &bih_l[ni*2]);
                    mma_bf16(acc[ni], axl, &bih_h[ni*2]);
                    mma_bf16(acc[ni], ahh, &bhh_h[ni*2]);
                    mma_bf16(acc[ni], ahh, &bhh_l[ni*2]);
                    mma_bf16(acc[ni], ahl, &bhh_h[ni*2]);
                }
            } else if (wq == 2) {
                uint32_t axh[4], axl[4], bh[4], bl[4];
                ldsm4(axh[0], axh[1], axh[2], axh[3], aXh + ao);
                ldsm4(axl[0], axl[1], axl[2], axl[3], aXl + ao);
                uint32_t oi = (uint32_t)(((32 + bRowIn)*72)*2) + coff;
                ldsm4(bh[0], bh[1], bh[2], bh[3], wBh + oi);
                ldsm4(bl[0], bl[1], bl[2], bl[3], wBl + oi);
                #pragma unroll
                for (int ni = 0; ni < 2; ni++) {
                    mma_bf16(acc[ni], axh, &bh[ni*2]);
                    mma_bf16(acc[ni], axh, &bl[ni*2]);
                    mma_bf16(acc[ni], axl, &bh[ni*2]);
                }
            } else {
                uint32_t ahh[4], ahl[4], bh[4], bl[4];
                ldsm4(ahh[0], ahh[1], ahh[2], ahh[3], aHh + ao);
                ldsm4(ahl[0], ahl[1], ahl[2], ahl[3], aHl + ao);
                uint32_t oh = (uint32_t)(((80 + bRowIn)*72)*2) + coff;
                ldsm4(bh[0], bh[1], bh[2], bh[3], wBh + oh);
                ldsm4(bl[0], bl[1], bl[2], bl[3], wBl + oh);
                #pragma unroll
                for (int ni = 0; ni < 2; ni++) {
                    mma_bf16(acc[ni], ahh, &bh[ni*2]);
                    mma_bf16(acc[ni], ahh, &bl[ni*2]);
                    mma_bf16(acc[ni], ahl, &bh[ni*2]);
                }
            }
        }
        __syncthreads();
    }

    {
        int r0 = wm16 + (lane >> 2);
        #pragma unroll
        for (int ni = 0; ni < 2; ni++) {
            int cb = ni*8 + (lane & 3)*2;
            sAcc[(wq*32 + r0)*17 + cb]       = acc[ni][0];
            sAcc[(wq*32 + r0)*17 + cb + 1]   = acc[ni][1];
            sAcc[(wq*32 + r0+8)*17 + cb]     = acc[ni][2];
            sAcc[(wq*32 + r0+8)*17 + cb + 1] = acc[ni][3];
        }
    }
    __syncthreads();

    #pragma unroll
    for (int j = 0; j < 2; j++) {
        int e = tid + j*256;
        int row = e >> 4, col = e & 15;
        float rv  = sAcc[(0*32 + row)*17 + col];
        float zv  = sAcc[(1*32 + row)*17 + col];
        float nxv = sAcc[(2*32 + row)*17 + col];
        float nhv = sAcc[(3*32 + row)*17 + col];
        int c = gc0 + col, b = row0 + row;
        float rr = 1.f/(1.f + expf(-(rv + __ldg(bih + c) + __ldg(bhh + c))));
        float zz = 1.f/(1.f + expf(-(zv + __ldg(bih + 512 + c) + __ldg(bhh + 512 + c))));
        float nn = tanhf(nxv + __ldg(bih + 1024 + c) + rr*(nhv + __ldg(bhh + 1024 + c)));
        float h = (1.f - zz)*nn + zz*hreg[j];
        hreg[j] = h;
        g_hd[1-p][l][(size_t)b*Hq + c] = h;
        __nv_bfloat16 bh = __float2bfloat16(h);
        g_hdh[1-p][l][(size_t)b*Hq + c] = bh;
        g_hdl[1-p][l][(size_t)b*Hq + c] = __float2bfloat16(h - __bfloat162float(bh));
    }
}

// single-pass attention: v kept in registers; sim in [-1,1] => constant shift 1.0
__device__ void dec_attn_stage(char* sm, int t, int p, float* __restrict__ attn_out) {
    float* qs   = (float*)sm;            // 512
    float* red  = qs + 512;              // 256
    float* se   = red + 256;             // 256
    float* pc   = se + 256;              // 8*512 partial contexts
    float* wsum = pc + 8*512;            // 8
    int b = blockIdx.x;
    int tid = threadIdx.x, wid = tid >> 5, lane = tid & 31;

    const float* q = g_hd[1-p][1] + (size_t)b*Hq;
    qs[tid]       = __ldcg(q + tid);
    qs[tid + 256] = __ldcg(q + tid + 256);
    __syncthreads();

    float ss = qs[tid]*qs[tid] + qs[tid+256]*qs[tid+256];
    red[tid] = ss; __syncthreads();
    for (int o = 128; o > 0; o >>= 1) { if (tid < o) red[tid] += red[tid + o]; __syncthreads(); }
    float qinv = 1.f / fmaxf(sqrtf(red[0]), 1e-8f);
    __syncthreads();

    float qf[16];
    #pragma unroll
    for (int j = 0; j < 4; j++) {
        float4 c = *(const float4*)(qs + lane*4 + j*128);
        qf[j*4+0]=c.x; qf[j*4+1]=c.y; qf[j*4+2]=c.z; qf[j*4+3]=c.w;
    }

    float acc[16];
    #pragma unroll
    for (int i = 0; i < 16; i++) acc[i] = 0.f;
    float ssum = 0.f;

    for (int li = 0; li < 32; li++) {
        int l = wid*32 + li;
        const float* vrow = g_v + ((size_t)l*Bq + b)*Hq;
        float vf[16];
        float d = 0.f;
        #pragma unroll
        for (int j = 0; j < 4; j++) {
            float4 a = __ldcg((const float4*)(vrow + lane*4 + j*128));
            vf[j*4+0]=a.x; vf[j*4+1]=a.y; vf[j*4+2]=a.z; vf[j*4+3]=a.w;
            d = fmaf(a.x, qf[j*4+0], d); d = fmaf(a.y, qf[j*4+1], d);
            d = fmaf(a.z, qf[j*4+2], d); d = fmaf(a.w, qf[j*4+3], d);
        }
        #pragma unroll
        for (int o = 16; o > 0; o >>= 1) d += __shfl_xor_sync(0xffffffffu, d, o);
        float vn = __ldg(&g_vn[(size_t)l*Bq + b]);
        float e = expf(d * qinv / vn - 1.0f);
        if (lane == 0) se[l] = e;
        ssum += e;
        #pragma unroll
        for (int i = 0; i < 16; i++) acc[i] = fmaf(e, vf[i], acc[i]);
    }

    #pragma unroll
    for (int j = 0; j < 4; j++) {
        float4 o4 = make_float4(acc[j*4], acc[j*4+1], acc[j*4+2], acc[j*4+3]);
        *(float4*)(pc + wid*512 + lane*4 + j*128) = o4;
    }
    if (lane == 0) wsum[wid] = ssum;
    __syncthreads();

    float tot = wsum[0]+wsum[1]+wsum[2]+wsum[3]+wsum[4]+wsum[5]+wsum[6]+wsum[7];
    float inv = 1.f / tot;

    float a0 = 0.f, a1 = 0.f;
    #pragma unroll
    for (int w = 0; w < 8; w++) {
        a0 += pc[w*512 + tid];
        a1 += pc[w*512 + tid + 256];
    }
    g_a[(size_t)b*Hq + tid]       = a0 * inv;
    g_a[(size_t)b*Hq + tid + 256] = a1 * inv;
    attn_out[((size_t)b*LCq + tid)*LTq + t] = se[tid] * inv;
}

__device__ void dec_attfc_stage(char* sm, int p,
        const float* __restrict__ Watt, const float* __restrict__ batt) {
    float* Xs  = (float*)sm;
    float* As2 = Xs + 32*33;
    float* Wqs = As2 + 32*33;
    float* Was = Wqs + 32*17;

    const float* X1 = g_hd[1-p][1];
    const float* X2 = g_a;
    int tid = threadIdx.x;
    int tx = tid & 15, ty = tid >> 4;
    int col0 = (blockIdx.x & 31) * 16, row0 = (blockIdx.x >> 5) * 32;

    float acc[2] = {0,0};
    for (int k0 = 0; k0 < Hq; k0 += KT) {
        {
            int r = tid >> 3, kk = (tid & 7) << 2;
            float4 x4 = __ldcg((const float4*)(X1 + (size_t)(row0 + r)*Hq + k0 + kk));
            Xs[kk*33 + r]=x4.x; Xs[(kk+1)*33 + r]=x4.y; Xs[(kk+2)*33 + r]=x4.z; Xs[(kk+3)*33 + r]=x4.w;
            float4 a4 = __ldcg((const float4*)(X2 + (size_t)(row0 + r)*Hq + k0 + kk));
            As2[kk*33 + r]=a4.x; As2[(kk+1)*33 + r]=a4.y; As2[(kk+2)*33 + r]=a4.z; As2[(kk+3)*33 + r]=a4.w;
        }
        #pragma unroll
        for (int j = 0; j < 2; j++) {
            int lin = tid + j*256;
            int c = lin >> 5, k = lin & 31;
            Wqs[k*17 + c] = __ldg(Watt + (size_t)(col0 + c)*2*Hq + k0 + k);
            Was[k*17 + c] = __ldg(Watt + (size_t)(col0 + c)*2*Hq + Hq + k0 + k);
        }
        __syncthreads();
        #pragma unroll
        for (int k = 0; k < KT; k++) {
            float wq = Wqs[k*17 + tx], wa = Was[k*17 + tx];
            #pragma unroll
            for (int i = 0; i < 2; i++) {
                acc[i] = fmaf(Xs[k*33 + ty + 16*i], wq, acc[i]);
                acc[i] = fmaf(As2[k*33 + ty + 16*i], wa, acc[i]);
            }
        }
        __syncthreads();
    }
    int c = col0 + tx;
    #pragma unroll
    for (int i = 0; i < 2; i++) {
        int b = row0 + ty + 16*i;
        g_hid[(size_t)b*Hq + c] = acc[i] + __ldg(batt + c);
    }
}

__device__ void dec_out_stage(char* sm, int t,
        const float* __restrict__ Wout, const float* __restrict__ bout,
        float* __restrict__ vecout) {
    float* hs = (float*)sm;
    float* lg = hs + 512;
    int b = blockIdx.x;
    int tid = threadIdx.x;
    hs[tid]       = __ldcg(&g_hid[(size_t)b*Hq + tid]);
    hs[tid + 256] = __ldcg(&g_hid[(size_t)b*Hq + tid + 256]);
    __syncthreads();

    int wid = tid >> 5, lane = tid & 31;
    for (int j = wid; j < Vq; j += 8) {
        float acc = 0.f;
        for (int k = lane; k < Hq; k += 32)
            acc = fmaf(hs[k], __ldg(Wout + (size_t)j*Hq + k), acc);
        #pragma unroll
        for (int o = 16; o > 0; o >>= 1) acc += __shfl_down_sync(0xffffffffu, acc, o);
        if (lane == 0) lg[j] = acc + __ldg(bout + j);
    }
    __syncthreads();
    if (tid < Vq) vecout[((size_t)b*LTq + t)*Vq + tid] = lg[tid];
    if (tid == 0) {
        int best = 0; float bv = lg[0];
        for (int j = 1; j < Vq; j++) { if (lg[j] > bv) { bv = lg[j]; best = j; } }
        g_vecin[b] = best;
    }
}

__global__ void __launch_bounds__(256, 1) k_dec_pers(
        const float* __restrict__ dec_bih, const float* __restrict__ dec_bhh,
        const float* __restrict__ Watt, const float* __restrict__ batt,
        const float* __restrict__ Wout, const float* __restrict__ bout,
        float* __restrict__ vecout, float* __restrict__ attn_out) {
    extern __shared__ char dsm[];
    int tid = threadIdx.x;
    int cg = blockIdx.x & 31, bg = blockIdx.x >> 5;
    int gc0 = cg * 16, row0 = bg * 32;

    float hdreg[2][2];
    #pragma unroll
    for (int l = 0; l < 2; l++)
        #pragma unroll
        for (int j = 0; j < 2; j++) {
            int e = tid + j*256;
            int row = e >> 4, col = e & 15;
            hdreg[l][j] = g_hd[0][l][(size_t)(row0 + row)*Hq + gc0 + col];
        }

    unsigned seq = 0;
    for (int t = 0; t < LTq; t++) {
        int p = t & 1;
        dec_gru_stage(dsm, 0, p, hdreg[0], g_dwih_h, g_dwih_l, g_dwhh_h, g_dwhh_l,
                      dec_bih, dec_bhh);
        dec_gridbar(++seq);
        dec_gru_stage(dsm, 1, p, hdreg[1],
                      g_dwih_h + (size_t)H3q*Hq, g_dwih_l + (size_t)H3q*Hq,
                      g_dwhh_h + (size_t)H3q*Hq, g_dwhh_l + (size_t)H3q*Hq,
                      dec_bih + H3q, dec_bhh + H3q);
        dec_gridbar(++seq);
        dec_attn_stage(dsm, t, p, attn_out);
        dec_gridbar(++seq);
        dec_attfc_stage(dsm, p, Watt, batt);
        dec_gridbar(++seq);
        dec_out_stage(dsm, t, Wout, bout, vecout);
        dec_gridbar(++seq);
    }
}

// ---------------- final hidden copy ----------------
__global__ void k_hfinal(float* __restrict__ out) {
    int idx = blockIdx.x * blockDim.x + threadIdx.x;
    if (idx < NLq*Bq*Hq) out[idx] = (&g_hd[0][0][0])[idx];
}

// ---------------- launch ----------------
extern "C" void kernel_launch(void* const* d_in, const int* in_sizes, int n_in,
                              void* d_out, int out_size) {
    const float* x        = (const float*)d_in[0];
    const float* emb      = (const float*)d_in[2];
    const float* W_enc    = (const float*)d_in[3];
    const float* b_enc    = (const float*)d_in[4];
    const float* enc0_Wih = (const float*)d_in[5];
    const float* enc0_Whh = (const float*)d_in[6];
    const float* enc0_bih = (const float*)d_in[7];
    const float* enc0_bhh = (const float*)d_in[8];
    const float* enc1_Wih = (const float*)d_in[9];
    const float* enc1_Whh = (const float*)d_in[10];
    const float* enc1_bih = (const float*)d_in[11];
    const float* enc1_bhh = (const float*)d_in[12];
    const float* W_bi     = (const float*)d_in[13];
    const float* b_bi     = (const float*)d_in[14];
    const float* dec_Wih  = (const float*)d_in[15];
    const float* dec_Whh  = (const float*)d_in[16];
    const float* dec_bih  = (const float*)d_in[17];
    const float* dec_bhh  = (const float*)d_in[18];
    const float* W_att    = (const float*)d_in[19];
    const float* b_att    = (const float*)d_in[20];
    const float* W_out    = (const float*)d_in[21];
    const float* b_out    = (const float*)d_in[22];

    float* out_vec  = (float*)d_out;
    float* out_h    = out_vec + (size_t)Bq*LTq*Vq;
    float* out_attn = out_h + (size_t)NLq*Bq*Hq;

    cudaFuncSetAttribute(k_enc_mma, cudaFuncAttributeMaxDynamicSharedMemorySize, ENC_SMEM);
    cudaFuncSetAttribute(k_dec_pers, cudaFuncAttributeMaxDynamicSharedMemorySize, DEC_SMEM);
    cudaFuncSetAttribute(k_gemm_mma, cudaFuncAttributeMaxDynamicSharedMemorySize, GEMM_SMEM);

    __nv_bfloat16 *xr_h, *xr_l, *y0_h, *y0_l, *y1_h, *y1_l, *w0_h, *w0_l, *w1_h, *w1_l, *wb_h, *wb_l;
    __nv_bfloat16 *dwih_h, *dwih_l, *dwhh_h, *dwhh_l, *emb_h, *emb_l;
    cudaGetSymbolAddress((void**)&xr_h, g_xr_h); cudaGetSymbolAddress((void**)&xr_l, g_xr_l);
    cudaGetSymbolAddress((void**)&y0_h, g_y0_h); cudaGetSymbolAddress((void**)&y0_l, g_y0_l);
    cudaGetSymbolAddress((void**)&y1_h, g_y1_h); cudaGetSymbolAddress((void**)&y1_l, g_y1_l);
    cudaGetSymbolAddress((void**)&w0_h, g_w0_h); cudaGetSymbolAddress((void**)&w0_l, g_w0_l);
    cudaGetSymbolAddress((void**)&w1_h, g_w1_h); cudaGetSymbolAddress((void**)&w1_l, g_w1_l);
    cudaGetSymbolAddress((void**)&wb_h, g_wb_h); cudaGetSymbolAddress((void**)&wb_l, g_wb_l);
    cudaGetSymbolAddress((void**)&dwih_h, g_dwih_h); cudaGetSymbolAddress((void**)&dwih_l, g_dwih_l);
    cudaGetSymbolAddress((void**)&dwhh_h, g_dwhh_h); cudaGetSymbolAddress((void**)&dwhh_l, g_dwhh_l);
    cudaGetSymbolAddress((void**)&emb_h, g_emb_h); cudaGetSymbolAddress((void**)&emb_l, g_emb_l);
    float* gi_f; cudaGetSymbolAddress((void**)&gi_f, g_gi);
    float* v_f;  cudaGetSymbolAddress((void**)&v_f,  g_v);

    k_proj<<<(Mq*Hq + 255)/256, 256>>>(x, W_enc, b_enc);                            // 0
    k_cvt<<<(2*H3q*Hq/4 + 255)/256, 256>>>(enc0_Wih, w0_h, w0_l, 2*H3q*Hq/4);       // 1
    k_gemm_mma<<<dim3(H3q/128, Mq/128, 2), 256, GEMM_SMEM>>>(                        // 2
        xr_h, xr_l, w0_h, w0_l, enc0_bih, gi_f,
        Hq, H3q, (size_t)H3q*Hq, H3q, (size_t)Mq*H3q);
    k_enc_mma<<<128, 256, ENC_SMEM>>>(enc0_Whh, enc0_bhh, 0);                        // 3 <- profiled
    k_cvt<<<(2*H3q*2*Hq/4 + 255)/256, 256>>>(enc1_Wih, w1_h, w1_l, 2*H3q*2*Hq/4);
    k_cvt<<<(Hq*2*Hq/4 + 255)/256, 256>>>(W_bi, wb_h, wb_l, Hq*2*Hq/4);
    k_cvt<<<(NLq*H3q*Hq/4 + 255)/256, 256>>>(dec_Wih, dwih_h, dwih_l, NLq*H3q*Hq/4);
    k_cvt<<<(NLq*H3q*Hq/4 + 255)/256, 256>>>(dec_Whh, dwhh_h, dwhh_l, NLq*H3q*Hq/4);
    k_cvt<<<(Vq*Hq/4 + 255)/256, 256>>>(emb, emb_h, emb_l, Vq*Hq/4);

    // layer 1
    k_gemm_mma<<<dim3(H3q/128, Mq/128, 2), 256, GEMM_SMEM>>>(
        y0_h, y0_l, w1_h, w1_l, enc1_bih, gi_f,
        2*Hq, H3q, (size_t)H3q*2*Hq, H3q, (size_t)Mq*H3q);
    k_enc_mma<<<128, 256, ENC_SMEM>>>(enc1_Whh, enc1_bhh, 1);

    // bi_fc + norms
    k_gemm_mma<<<dim3(Hq/128, Mq/128, 1), 256, GEMM_SMEM>>>(
        y1_h, y1_l, wb_h, wb_l, b_bi, v_f,
        2*Hq, Hq, 0, 0, 0);
    k_vn<<<Mq, 128>>>();

    // persistent decoder
    k_initdec<<<(Bq*Hq + 255)/256, 256>>>();
    k_dec_pers<<<128, 256, DEC_SMEM>>>(dec_bih, dec_bhh, W_att, b_att,
                                       W_out, b_out, out_vec, out_attn);
    k_hfinal<<<(NLq*Bq*Hq + 255)/256, 256>>>(out_h);
    (void)in_sizes; (void)n_in; (void)out_size;
}